// round 12
// baseline (speedup 1.0000x reference)
#include <cuda_runtime.h>
#include <cstdint>

// ---------------------------------------------------------------------------
// Performer causal linear attention, fp32, FFMA2 cores.
// R11 = R9 (fused k_featKC + k_featQ + streaming fused k_out)
//       + MLP-4 prefetched k_scan from R10.
// b=2 h=8 n=4096 d=64 r=256 chunk=64 -> 65536 tokens, 1024 chunks
// g_sums record per tile (SSTRIDE=16768 floats):
//   [0,16384)  Sraw (later scanned S_pre)   [16384,16640) zraw (later z_pre)
//   [16640,16704) vsum                      [16704] m_c (not scanned)
// ---------------------------------------------------------------------------

constexpr int D_ = 64;
constexpr int R_ = 256;
constexpr int C_ = 64;
constexpr int NTILES = 1024;
constexpr int SSTRIDE = 16768;

__device__ __align__(16) float g_projT[D_ * R_];
__device__ __align__(16) float g_qp[(size_t)NTILES * C_ * R_];
__device__ __align__(16) float g_kf[(size_t)NTILES * C_ * R_];   // E values
__device__ __align__(16) float g_sums[(size_t)NTILES * SSTRIDE];
__device__ unsigned g_maxkey;

#define NORM_F   0.35355339059327373f
#define DIAGC_F  0.0625f
#define RATIO_F  0.0625f
#define KEPS_F   1e-4f
#define AEPS_F   1e-6f
#define REPS_F   (RATIO_F * KEPS_F)

typedef unsigned long long u64;

__device__ __forceinline__ u64 pk2(float x) {
    u64 r; asm("mov.b64 %0, {%1, %1};" : "=l"(r) : "f"(x)); return r;
}
__device__ __forceinline__ u64 pkxy(float x, float y) {
    u64 r; asm("mov.b64 %0, {%1, %2};" : "=l"(r) : "f"(x), "f"(y)); return r;
}
__device__ __forceinline__ void fma2(u64& d, u64 a, u64 b) {
    asm("fma.rn.f32x2 %0, %1, %2, %0;" : "+l"(d) : "l"(a), "l"(b));
}
__device__ __forceinline__ float2 up2(u64 a) {
    float2 f; asm("mov.b64 {%0, %1}, %2;" : "=f"(f.x), "=f"(f.y) : "l"(a));
    return f;
}
__device__ __forceinline__ float fexp(float x) {
    x = fmaxf(x, -87.0f);
    float t  = x * 1.4426950408889634f;
    float nf = rintf(t);
    float f  = t - nf;
    float p  = 1.5403530393e-4f;
    p = fmaf(p, f, 1.3333558146e-3f);
    p = fmaf(p, f, 9.6181291076e-3f);
    p = fmaf(p, f, 5.5504108665e-2f);
    p = fmaf(p, f, 2.4022650696e-1f);
    p = fmaf(p, f, 6.9314718056e-1f);
    p = fmaf(p, f, 1.0f);
    int n = (int)nf;
    return p * __int_as_float((n + 127) << 23);
}
__device__ __forceinline__ unsigned fkey(float f) {
    unsigned u = __float_as_uint(f);
    return (u & 0x80000000u) ? ~u : (u | 0x80000000u);
}
__device__ __forceinline__ float fdec(unsigned k) {
    return (k & 0x80000000u) ? __uint_as_float(k ^ 0x80000000u)
                             : __uint_as_float(~k);
}

// ---------------------------------------------------------------------------
__global__ void k_prep(const float* __restrict__ proj) {
    int tid = threadIdx.x;
    for (int idx = tid; idx < D_ * R_; idx += blockDim.x) {
        int kk = idx / R_, rr = idx % R_;
        g_projT[idx] = proj[rr * D_ + kk] * NORM_F;
    }
    if (tid == 0) g_maxkey = 0u;
}

// ---------------------------------------------------------------------------
__global__ void __launch_bounds__(256) k_featQ(const float* __restrict__ x) {
    extern __shared__ float sm[];
    float* pT = sm;
    float* xT = sm + 16384;
    float* dg = xT + 64 * 68;
    const int tile = blockIdx.x, tid = threadIdx.x;
    const float* xg = x + (size_t)tile * (C_ * D_);
    float* dst = g_qp + (size_t)tile * (C_ * R_);

#pragma unroll
    for (int i = 0; i < 16; i++) {
        int i4 = tid + i * 256;
        reinterpret_cast<float4*>(pT)[i4] =
            reinterpret_cast<const float4*>(g_projT)[i4];
    }
#pragma unroll
    for (int i = 0; i < 4; i++) {
        int i4 = tid + i * 256;
        float4 vv = reinterpret_cast<const float4*>(xg)[i4];
        int t = (4 * i4) >> 6, kk = (4 * i4) & 63;
        xT[(kk + 0) * 68 + t] = vv.x;
        xT[(kk + 1) * 68 + t] = vv.y;
        xT[(kk + 2) * 68 + t] = vv.z;
        xT[(kk + 3) * 68 + t] = vv.w;
    }
    __syncthreads();
    if (tid < 64) {
        float s = 0.f;
#pragma unroll
        for (int kk = 0; kk < 64; kk++) {
            float vv = xT[kk * 68 + tid];
            s = fmaf(vv, vv, s);
        }
        dg[tid] = DIAGC_F * s;
    }
    __syncthreads();

    const int tr = tid >> 5, tc = tid & 31;
    const int t0 = tr * 8, r0 = tc * 4;
    u64 acc[8][4];
#pragma unroll
    for (int i = 0; i < 8; i++)
#pragma unroll
        for (int j = 0; j < 4; j++) acc[i][j] = 0ull;

#pragma unroll 4
    for (int kk = 0; kk < 64; kk++) {
        float4 a0 = *reinterpret_cast<const float4*>(xT + kk * 68 + t0);
        float4 a1 = *reinterpret_cast<const float4*>(xT + kk * 68 + t0 + 4);
        ulonglong2 B0 = *reinterpret_cast<const ulonglong2*>(pT + kk * 256 + r0);
        ulonglong2 B1 = *reinterpret_cast<const ulonglong2*>(pT + kk * 256 + 128 + r0);
        u64 b[4] = {B0.x, B0.y, B1.x, B1.y};
        u64 ap[8] = {pk2(a0.x), pk2(a0.y), pk2(a0.z), pk2(a0.w),
                     pk2(a1.x), pk2(a1.y), pk2(a1.z), pk2(a1.w)};
#pragma unroll
        for (int i = 0; i < 8; i++)
#pragma unroll
            for (int j = 0; j < 4; j++) fma2(acc[i][j], ap[i], b[j]);
    }

#pragma unroll
    for (int i = 0; i < 8; i++) {
        float2 p0 = up2(acc[i][0]), p1 = up2(acc[i][1]);
        float2 p2 = up2(acc[i][2]), p3 = up2(acc[i][3]);
        float a8[8] = {p0.x, p0.y, p1.x, p1.y, p2.x, p2.y, p3.x, p3.y};
        int t = t0 + i;
        float m = a8[0];
#pragma unroll
        for (int j = 1; j < 8; j++) m = fmaxf(m, a8[j]);
#pragma unroll
        for (int off = 16; off >= 1; off >>= 1)
            m = fmaxf(m, __shfl_xor_sync(0xffffffffu, m, off));
        const float dgi = dg[t] + m;
        float4 o0, o1;
        o0.x = RATIO_F * (fexp(a8[0] - dgi) + KEPS_F);
        o0.y = RATIO_F * (fexp(a8[1] - dgi) + KEPS_F);
        o0.z = RATIO_F * (fexp(a8[2] - dgi) + KEPS_F);
        o0.w = RATIO_F * (fexp(a8[3] - dgi) + KEPS_F);
        o1.x = RATIO_F * (fexp(a8[4] - dgi) + KEPS_F);
        o1.y = RATIO_F * (fexp(a8[5] - dgi) + KEPS_F);
        o1.z = RATIO_F * (fexp(a8[6] - dgi) + KEPS_F);
        o1.w = RATIO_F * (fexp(a8[7] - dgi) + KEPS_F);
        *reinterpret_cast<float4*>(dst + t * 256 + r0) = o0;
        *reinterpret_cast<float4*>(dst + t * 256 + 128 + r0) = o1;
    }
}

// ---------------------------------------------------------------------------
__global__ void __launch_bounds__(256) k_featKC(const float* __restrict__ x,
                                                const float* __restrict__ v) {
    extern __shared__ float sm[];
    float* pT   = sm;                 // [64][256]; later E [t][r]
    float* xT   = sm + 16384;         // [64][68]
    float* sv   = sm + 20736;         // [64][64]
    float* dg   = sm + 24832;         // [64]
    float* wrd  = sm + 24896;         // [8]
    float* wra  = sm + 24904;         // [8]
    float* mcs  = sm + 24912;         // [1]
    float* E    = pT;
    const int tile = blockIdx.x, tid = threadIdx.x;
    const float* xg = x + (size_t)tile * (C_ * D_);
    float* dst = g_kf + (size_t)tile * (C_ * R_);

#pragma unroll
    for (int i = 0; i < 16; i++) {
        int i4 = tid + i * 256;
        reinterpret_cast<float4*>(pT)[i4] =
            reinterpret_cast<const float4*>(g_projT)[i4];
    }
#pragma unroll
    for (int i = 0; i < 4; i++) {
        int i4 = tid + i * 256;
        float4 vv = reinterpret_cast<const float4*>(xg)[i4];
        int t = (4 * i4) >> 6, kk = (4 * i4) & 63;
        xT[(kk + 0) * 68 + t] = vv.x;
        xT[(kk + 1) * 68 + t] = vv.y;
        xT[(kk + 2) * 68 + t] = vv.z;
        xT[(kk + 3) * 68 + t] = vv.w;
    }
    const float* vg = v + (size_t)tile * (C_ * D_);
#pragma unroll
    for (int i = 0; i < 4; i++) {
        int i4 = tid + i * 256;
        reinterpret_cast<float4*>(sv)[i4] =
            reinterpret_cast<const float4*>(vg)[i4];
    }
    __syncthreads();
    if (tid < 64) {
        float s = 0.f;
#pragma unroll
        for (int kk = 0; kk < 64; kk++) {
            float vv = xT[kk * 68 + tid];
            s = fmaf(vv, vv, s);
        }
        dg[tid] = DIAGC_F * s;
    }
    __syncthreads();

    const int tr = tid >> 5, tc = tid & 31;
    const int t0 = tr * 8, r0 = tc * 4;
    u64 acc[8][4];
#pragma unroll
    for (int i = 0; i < 8; i++)
#pragma unroll
        for (int j = 0; j < 4; j++) acc[i][j] = 0ull;

#pragma unroll 4
    for (int kk = 0; kk < 64; kk++) {
        float4 a0 = *reinterpret_cast<const float4*>(xT + kk * 68 + t0);
        float4 a1 = *reinterpret_cast<const float4*>(xT + kk * 68 + t0 + 4);
        ulonglong2 B0 = *reinterpret_cast<const ulonglong2*>(pT + kk * 256 + r0);
        ulonglong2 B1 = *reinterpret_cast<const ulonglong2*>(pT + kk * 256 + 128 + r0);
        u64 b[4] = {B0.x, B0.y, B1.x, B1.y};
        u64 ap[8] = {pk2(a0.x), pk2(a0.y), pk2(a0.z), pk2(a0.w),
                     pk2(a1.x), pk2(a1.y), pk2(a1.z), pk2(a1.w)};
#pragma unroll
        for (int i = 0; i < 8; i++)
#pragma unroll
            for (int j = 0; j < 4; j++) fma2(acc[i][j], ap[i], b[j]);
    }

    float bmd = -3.0e38f, bma = -3.0e38f;
#pragma unroll
    for (int i = 0; i < 8; i++) {
        float2 p0 = up2(acc[i][0]), p1 = up2(acc[i][1]);
        float2 p2 = up2(acc[i][2]), p3 = up2(acc[i][3]);
        float rm = fmaxf(fmaxf(fmaxf(p0.x, p0.y), fmaxf(p1.x, p1.y)),
                         fmaxf(fmaxf(p2.x, p2.y), fmaxf(p3.x, p3.y)));
        bmd = fmaxf(bmd, rm);
        bma = fmaxf(bma, rm - dg[t0 + i]);
    }
#pragma unroll
    for (int off = 16; off >= 1; off >>= 1) {
        bmd = fmaxf(bmd, __shfl_xor_sync(0xffffffffu, bmd, off));
        bma = fmaxf(bma, __shfl_xor_sync(0xffffffffu, bma, off));
    }
    if ((tid & 31) == 0) { wrd[tid >> 5] = bmd; wra[tid >> 5] = bma; }
    __syncthreads();
    if (tid == 0) {
        float md = wrd[0], ma = wra[0];
#pragma unroll
        for (int w = 1; w < 8; w++) {
            md = fmaxf(md, wrd[w]);
            ma = fmaxf(ma, wra[w]);
        }
        atomicMax(&g_maxkey, fkey(md));
        mcs[0] = ma;
    }
    __syncthreads();
    const float mc = mcs[0];

#pragma unroll
    for (int i = 0; i < 8; i++) {
        float2 p0 = up2(acc[i][0]), p1 = up2(acc[i][1]);
        float2 p2 = up2(acc[i][2]), p3 = up2(acc[i][3]);
        float a8[8] = {p0.x, p0.y, p1.x, p1.y, p2.x, p2.y, p3.x, p3.y};
        int t = t0 + i;
        const float sh = dg[t] + mc;
        float4 o0, o1;
        o0.x = fexp(a8[0] - sh); o0.y = fexp(a8[1] - sh);
        o0.z = fexp(a8[2] - sh); o0.w = fexp(a8[3] - sh);
        o1.x = fexp(a8[4] - sh); o1.y = fexp(a8[5] - sh);
        o1.z = fexp(a8[6] - sh); o1.w = fexp(a8[7] - sh);
        *reinterpret_cast<float4*>(E + t * 256 + r0) = o0;
        *reinterpret_cast<float4*>(E + t * 256 + 128 + r0) = o1;
        *reinterpret_cast<float4*>(dst + t * 256 + r0) = o0;
        *reinterpret_cast<float4*>(dst + t * 256 + 128 + r0) = o1;
    }
    __syncthreads();

    const int ri = tid >> 3, ei = tid & 7;
    const int rr0 = ri * 8, e0 = ei * 8;
    u64 acc2[8][4];
#pragma unroll
    for (int i = 0; i < 8; i++)
#pragma unroll
        for (int j = 0; j < 4; j++) acc2[i][j] = 0ull;

#pragma unroll 4
    for (int t = 0; t < 64; t++) {
        float4 a0 = *reinterpret_cast<const float4*>(E + t * 256 + rr0);
        float4 a1 = *reinterpret_cast<const float4*>(E + t * 256 + rr0 + 4);
        ulonglong2 B0 = *reinterpret_cast<const ulonglong2*>(sv + t * 64 + e0);
        ulonglong2 B1 = *reinterpret_cast<const ulonglong2*>(sv + t * 64 + e0 + 4);
        u64 b[4] = {B0.x, B0.y, B1.x, B1.y};
        u64 ap[8] = {pk2(a0.x), pk2(a0.y), pk2(a0.z), pk2(a0.w),
                     pk2(a1.x), pk2(a1.y), pk2(a1.z), pk2(a1.w)};
#pragma unroll
        for (int i = 0; i < 8; i++)
#pragma unroll
            for (int j = 0; j < 4; j++) fma2(acc2[i][j], ap[i], b[j]);
    }
    float zs = 0.f;
#pragma unroll 8
    for (int t = 0; t < 64; t++) zs += E[t * 256 + tid];

    float* So = g_sums + (size_t)tile * SSTRIDE;
#pragma unroll
    for (int i = 0; i < 8; i++) {
        int r = rr0 + i;
        float2 p0 = up2(acc2[i][0]), p1 = up2(acc2[i][1]);
        float2 p2 = up2(acc2[i][2]), p3 = up2(acc2[i][3]);
        *reinterpret_cast<float4*>(So + r * 64 + e0) =
            make_float4(p0.x, p0.y, p1.x, p1.y);
        *reinterpret_cast<float4*>(So + r * 64 + e0 + 4) =
            make_float4(p2.x, p2.y, p3.x, p3.y);
    }
    So[16384 + tid] = zs;
    if (tid < 64) {
        float vs = 0.f;
#pragma unroll 8
        for (int t = 0; t < 64; t++) vs += sv[t * 64 + tid];
        So[16640 + tid] = vs;
    }
    if (tid == 0) So[16704] = mc;
}

// ---------------------------------------------------------------------------
// Prefetched rescaling scan (MLP=4 over the chunk chain).
__global__ void __launch_bounds__(256) k_scan() {
    const int head = blockIdx.x / 65, grp = blockIdx.x % 65;
    const int idx = grp * 256 + threadIdx.x;
    const bool isS = idx < 16384;
    const int e = idx & 63;
    const float stab = fdec(g_maxkey);
    const size_t base = (size_t)head * 64 * SSTRIDE;

    float val[4];
#pragma unroll
    for (int p = 0; p < 4; p++) {
        size_t rec = base + (size_t)p * SSTRIDE;
        float raw = g_sums[rec + idx];
        float mcv = g_sums[rec + 16704];
        float vsv = isS ? g_sums[rec + 16640 + e] : 64.0f;
        val[p] = fmaf(RATIO_F * fexp(mcv - stab), raw, REPS_F * vsv);
    }
    float run = 0.f;
#pragma unroll 4
    for (int c = 0; c < 64; c++) {
        float cur = val[c & 3];
        if (c + 4 < 64) {
            size_t rec = base + (size_t)(c + 4) * SSTRIDE;
            float raw = g_sums[rec + idx];
            float mcv = g_sums[rec + 16704];
            float vsv = isS ? g_sums[rec + 16640 + e] : 64.0f;
            val[c & 3] = fmaf(RATIO_F * fexp(mcv - stab), raw, REPS_F * vsv);
        }
        g_sums[base + (size_t)c * SSTRIDE + idx] = run;
        run += cur;
    }
}

// ---------------------------------------------------------------------------
// Fused streaming k_out (48.5KB smem, 2 CTAs/SM):
// r in 4 chunks of 64; masked-QK^T, Q@S_pre, denominator share q loads.
// kp reconstructed as s1*E + REPS (no exp).
__global__ void __launch_bounds__(256, 2) k_out(const float* __restrict__ v,
                                                float* __restrict__ out) {
    extern __shared__ float sm[];
    float* q_c = sm;            // [64][64] swizzled; later A_s
    float* k_c = sm + 4096;     // [64][64] swizzled
    float* s_c = sm + 8192;     // [64][64] natural;  later v_s
    float* sz  = sm + 12288;    // [64]
    float* sDi = sz + 64;       // [64]
    float* A_s = q_c;
    float* v_s = s_c;

    const int tile = blockIdx.x, tid = threadIdx.x;
    const float4* qg4 = reinterpret_cast<const float4*>(g_qp + (size_t)tile * (C_ * R_));
    const float4* kg4 = reinterpret_cast<const float4*>(g_kf + (size_t)tile * (C_ * R_));
    const float*  Sg  = g_sums + (size_t)tile * SSTRIDE;
    const float4* Sg4 = reinterpret_cast<const float4*>(Sg);
    const float s1 = RATIO_F * fexp(Sg[16704] - fdec(g_maxkey));

    const int tg = tid >> 4;    // t = tg + 16*i
    const int mg = tid & 15;    // m = mg + 16*j ; e0 = mg*4
    const int e0 = mg * 4;

    u64 accA[4][4], accO[4][2];
#pragma unroll
    for (int i = 0; i < 4; i++) {
#pragma unroll
        for (int j = 0; j < 4; j++) accA[i][j] = 0ull;
        accO[i][0] = 0ull; accO[i][1] = 0ull;
    }
    float dp[4] = {0.f, 0.f, 0.f, 0.f};

#pragma unroll 1
    for (int rc = 0; rc < 4; rc++) {
        __syncthreads();
#pragma unroll
        for (int i = 0; i < 4; i++) {
            int i4 = tid + i * 256;
            int t = i4 >> 4, r4 = i4 & 15;
            int u = r4 ^ (t & 15);
            float4 a = qg4[t * 64 + rc * 16 + r4];
            *reinterpret_cast<float4*>(q_c + t * 64 + u * 4) = a;
            float4 b = kg4[t * 64 + rc * 16 + r4];
            b.x = fmaf(s1, b.x, REPS_F);
            b.y = fmaf(s1, b.y, REPS_F);
            b.z = fmaf(s1, b.z, REPS_F);
            b.w = fmaf(s1, b.w, REPS_F);
            *reinterpret_cast<float4*>(k_c + t * 64 + u * 4) = b;
            reinterpret_cast<float4*>(s_c)[i4] = Sg4[rc * 1024 + i4];
        }
        if (tid < 64) sz[tid] = Sg[16384 + rc * 64 + tid] + AEPS_F;
        __syncthreads();

#pragma unroll 2
        for (int rr = 0; rr < 16; rr++) {
            float4 aq[4];
            ulonglong2 bk[4], bs[4];
            const int qoff = (rr ^ tg) << 2;
#pragma unroll
            for (int i = 0; i < 4; i++)
                aq[i] = *reinterpret_cast<const float4*>(
                    q_c + (tg + 16 * i) * 64 + qoff);
#pragma unroll
            for (int j = 0; j < 4; j++)
                bk[j] = *reinterpret_cast<const ulonglong2*>(
                    k_c + (mg + 16 * j) * 64 + ((rr ^ mg) << 2));
#pragma unroll
            for (int c = 0; c < 4; c++)
                bs[c] = *reinterpret_cast<const ulonglong2*>(
                    s_c + (rr * 4 + c) * 64 + e0);
#pragma unroll
            for (int i = 0; i < 4; i++) {
                u64 alo = pkxy(aq[i].x, aq[i].y);
                u64 ahi = pkxy(aq[i].z, aq[i].w);
#pragma unroll
                for (int j = 0; j < 4; j++) {
                    fma2(accA[i][j], alo, bk[j].x);
                    fma2(accA[i][j], ahi, bk[j].y);
                }
                u64 p;
                p = pk2(aq[i].x); fma2(accO[i][0], p, bs[0].x); fma2(accO[i][1], p, bs[0].y);
                p = pk2(aq[i].y); fma2(accO[i][0], p, bs[1].x); fma2(accO[i][1], p, bs[1].y);
                p = pk2(aq[i].z); fma2(accO[i][0], p, bs[2].x); fma2(accO[i][1], p, bs[2].y);
                p = pk2(aq[i].w); fma2(accO[i][0], p, bs[3].x); fma2(accO[i][1], p, bs[3].y);
            }
            if (mg == 0) {
                const float* zz = sz + rr * 4;
#pragma unroll
                for (int i = 0; i < 4; i++) {
                    dp[i] = fmaf(aq[i].x, zz[0], dp[i]);
                    dp[i] = fmaf(aq[i].y, zz[1], dp[i]);
                    dp[i] = fmaf(aq[i].z, zz[2], dp[i]);
                    dp[i] = fmaf(aq[i].w, zz[3], dp[i]);
                }
            }
        }
    }
    __syncthreads();

    // mask A, denominators, A -> A_s(=q_c); v -> v_s(=s_c)
#pragma unroll
    for (int i = 0; i < 4; i++) {
        int t = tg + 16 * i;
        float af[4], p = 0.f;
#pragma unroll
        for (int j = 0; j < 4; j++) {
            float2 h = up2(accA[i][j]);
            af[j] = h.x + h.y;
            int m = mg + 16 * j;
            if (m > t) af[j] = 0.f;
            p += af[j];
        }
#pragma unroll
        for (int off = 1; off < 16; off <<= 1)
            p += __shfl_xor_sync(0xffffffffu, p, off, 16);
#pragma unroll
        for (int j = 0; j < 4; j++) {
            int m = mg + 16 * j;
            A_s[t * 64 + (((m >> 2) ^ (t & 15)) << 2) + (m & 3)] = af[j];
        }
        if (mg == 0) sDi[t] = 1.0f / (p + dp[i]);
    }
    const float4* vg4 = reinterpret_cast<const float4*>(v + (size_t)tile * (C_ * D_));
#pragma unroll
    for (int i = 0; i < 4; i++) {
        int i4 = tid + i * 256;
        reinterpret_cast<float4*>(v_s)[i4] = vg4[i4];
    }
    __syncthreads();

    // Phase B: O += A @ V
#pragma unroll 2
    for (int mm = 0; mm < 16; mm++) {
        float4 a[4];
        ulonglong2 b[4];
#pragma unroll
        for (int i = 0; i < 4; i++)
            a[i] = *reinterpret_cast<const float4*>(
                A_s + (tg + 16 * i) * 64 + ((mm ^ tg) << 2));
#pragma unroll
        for (int c = 0; c < 4; c++)
            b[c] = *reinterpret_cast<const ulonglong2*>(
                v_s + (mm * 4 + c) * 64 + e0);
#pragma unroll
        for (int i = 0; i < 4; i++) {
            u64 p;
            p = pk2(a[i].x); fma2(accO[i][0], p, b[0].x); fma2(accO[i][1], p, b[0].y);
            p = pk2(a[i].y); fma2(accO[i][0], p, b[1].x); fma2(accO[i][1], p, b[1].y);
            p = pk2(a[i].z); fma2(accO[i][0], p, b[2].x); fma2(accO[i][1], p, b[2].y);
            p = pk2(a[i].w); fma2(accO[i][0], p, b[3].x); fma2(accO[i][1], p, b[3].y);
        }
    }

    float* og = out + (size_t)tile * (C_ * D_);
#pragma unroll
    for (int i = 0; i < 4; i++) {
        int t = tg + 16 * i;
        float di = sDi[t];
        float2 h0 = up2(accO[i][0]), h1 = up2(accO[i][1]);
        *reinterpret_cast<float4*>(og + t * 64 + e0) =
            make_float4(h0.x * di, h0.y * di, h1.x * di, h1.y * di);
    }
}

// ---------------------------------------------------------------------------
extern "C" void kernel_launch(void* const* d_in, const int* in_sizes, int n_in,
                              void* d_out, int out_size) {
    const float* q    = (const float*)d_in[0];
    const float* k    = (const float*)d_in[1];
    const float* v    = (const float*)d_in[2];
    const float* proj = (const float*)d_in[3];
    float* out = (float*)d_out;

    const int SMEM_Q  = (16384 + 64 * 68 + 64) * 4;   // ~83 KB
    const int SMEM_KC = (24913 + 3) * 4;              // ~99.7 KB
    const int SMEM_O  = (4096 * 3 + 64 + 64) * 4;     // ~48.5 KB

    cudaFuncSetAttribute(k_featQ,  cudaFuncAttributeMaxDynamicSharedMemorySize, SMEM_Q);
    cudaFuncSetAttribute(k_featKC, cudaFuncAttributeMaxDynamicSharedMemorySize, SMEM_KC);
    cudaFuncSetAttribute(k_out,    cudaFuncAttributeMaxDynamicSharedMemorySize, SMEM_O);

    k_prep<<<1, 256>>>(proj);
    k_featQ<<<NTILES, 256, SMEM_Q>>>(q);
    k_featKC<<<NTILES, 256, SMEM_KC>>>(k, v);
    k_scan<<<1040, 256>>>();
    k_out<<<NTILES, 256, SMEM_O>>>(v, out);
}

// round 13
// speedup vs baseline: 1.5585x; 1.5585x over previous
#include <cuda_runtime.h>
#include <cstdint>

// ---------------------------------------------------------------------------
// Performer causal linear attention, fp32, FFMA2 cores.
// R13 = R11 architecture (k_featQ + fused k_featKC + streaming fused k_out)
//       with strength-reduced MLP-4 prefetch k_scan (pointer increments).
// b=2 h=8 n=4096 d=64 r=256 chunk=64 -> 65536 tokens, 1024 chunks
// g_sums record per tile (SSTRIDE=16768 floats):
//   [0,16384)  Sraw (later scanned S_pre)   [16384,16640) zraw (later z_pre)
//   [16640,16704) vsum                      [16704] m_c (not scanned)
// ---------------------------------------------------------------------------

constexpr int D_ = 64;
constexpr int R_ = 256;
constexpr int C_ = 64;
constexpr int NTILES = 1024;
constexpr int SSTRIDE = 16768;

__device__ __align__(16) float g_projT[D_ * R_];
__device__ __align__(16) float g_qp[(size_t)NTILES * C_ * R_];
__device__ __align__(16) float g_kf[(size_t)NTILES * C_ * R_];   // E values
__device__ __align__(16) float g_sums[(size_t)NTILES * SSTRIDE];
__device__ unsigned g_maxkey;

#define NORM_F   0.35355339059327373f
#define DIAGC_F  0.0625f
#define RATIO_F  0.0625f
#define KEPS_F   1e-4f
#define AEPS_F   1e-6f
#define REPS_F   (RATIO_F * KEPS_F)

typedef unsigned long long u64;

__device__ __forceinline__ u64 pk2(float x) {
    u64 r; asm("mov.b64 %0, {%1, %1};" : "=l"(r) : "f"(x)); return r;
}
__device__ __forceinline__ u64 pkxy(float x, float y) {
    u64 r; asm("mov.b64 %0, {%1, %2};" : "=l"(r) : "f"(x), "f"(y)); return r;
}
__device__ __forceinline__ void fma2(u64& d, u64 a, u64 b) {
    asm("fma.rn.f32x2 %0, %1, %2, %0;" : "+l"(d) : "l"(a), "l"(b));
}
__device__ __forceinline__ float2 up2(u64 a) {
    float2 f; asm("mov.b64 {%0, %1}, %2;" : "=f"(f.x), "=f"(f.y) : "l"(a));
    return f;
}
__device__ __forceinline__ float fexp(float x) {
    x = fmaxf(x, -87.0f);
    float t  = x * 1.4426950408889634f;
    float nf = rintf(t);
    float f  = t - nf;
    float p  = 1.5403530393e-4f;
    p = fmaf(p, f, 1.3333558146e-3f);
    p = fmaf(p, f, 9.6181291076e-3f);
    p = fmaf(p, f, 5.5504108665e-2f);
    p = fmaf(p, f, 2.4022650696e-1f);
    p = fmaf(p, f, 6.9314718056e-1f);
    p = fmaf(p, f, 1.0f);
    int n = (int)nf;
    return p * __int_as_float((n + 127) << 23);
}
__device__ __forceinline__ unsigned fkey(float f) {
    unsigned u = __float_as_uint(f);
    return (u & 0x80000000u) ? ~u : (u | 0x80000000u);
}
__device__ __forceinline__ float fdec(unsigned k) {
    return (k & 0x80000000u) ? __uint_as_float(k ^ 0x80000000u)
                             : __uint_as_float(~k);
}

// ---------------------------------------------------------------------------
__global__ void k_prep(const float* __restrict__ proj) {
    int tid = threadIdx.x;
    for (int idx = tid; idx < D_ * R_; idx += blockDim.x) {
        int kk = idx / R_, rr = idx % R_;
        g_projT[idx] = proj[rr * D_ + kk] * NORM_F;
    }
    if (tid == 0) g_maxkey = 0u;
}

// ---------------------------------------------------------------------------
__global__ void __launch_bounds__(256) k_featQ(const float* __restrict__ x) {
    extern __shared__ float sm[];
    float* pT = sm;
    float* xT = sm + 16384;
    float* dg = xT + 64 * 68;
    const int tile = blockIdx.x, tid = threadIdx.x;
    const float* xg = x + (size_t)tile * (C_ * D_);
    float* dst = g_qp + (size_t)tile * (C_ * R_);

#pragma unroll
    for (int i = 0; i < 16; i++) {
        int i4 = tid + i * 256;
        reinterpret_cast<float4*>(pT)[i4] =
            reinterpret_cast<const float4*>(g_projT)[i4];
    }
#pragma unroll
    for (int i = 0; i < 4; i++) {
        int i4 = tid + i * 256;
        float4 vv = reinterpret_cast<const float4*>(xg)[i4];
        int t = (4 * i4) >> 6, kk = (4 * i4) & 63;
        xT[(kk + 0) * 68 + t] = vv.x;
        xT[(kk + 1) * 68 + t] = vv.y;
        xT[(kk + 2) * 68 + t] = vv.z;
        xT[(kk + 3) * 68 + t] = vv.w;
    }
    __syncthreads();
    if (tid < 64) {
        float s = 0.f;
#pragma unroll
        for (int kk = 0; kk < 64; kk++) {
            float vv = xT[kk * 68 + tid];
            s = fmaf(vv, vv, s);
        }
        dg[tid] = DIAGC_F * s;
    }
    __syncthreads();

    const int tr = tid >> 5, tc = tid & 31;
    const int t0 = tr * 8, r0 = tc * 4;
    u64 acc[8][4];
#pragma unroll
    for (int i = 0; i < 8; i++)
#pragma unroll
        for (int j = 0; j < 4; j++) acc[i][j] = 0ull;

#pragma unroll 4
    for (int kk = 0; kk < 64; kk++) {
        float4 a0 = *reinterpret_cast<const float4*>(xT + kk * 68 + t0);
        float4 a1 = *reinterpret_cast<const float4*>(xT + kk * 68 + t0 + 4);
        ulonglong2 B0 = *reinterpret_cast<const ulonglong2*>(pT + kk * 256 + r0);
        ulonglong2 B1 = *reinterpret_cast<const ulonglong2*>(pT + kk * 256 + 128 + r0);
        u64 b[4] = {B0.x, B0.y, B1.x, B1.y};
        u64 ap[8] = {pk2(a0.x), pk2(a0.y), pk2(a0.z), pk2(a0.w),
                     pk2(a1.x), pk2(a1.y), pk2(a1.z), pk2(a1.w)};
#pragma unroll
        for (int i = 0; i < 8; i++)
#pragma unroll
            for (int j = 0; j < 4; j++) fma2(acc[i][j], ap[i], b[j]);
    }

#pragma unroll
    for (int i = 0; i < 8; i++) {
        float2 p0 = up2(acc[i][0]), p1 = up2(acc[i][1]);
        float2 p2 = up2(acc[i][2]), p3 = up2(acc[i][3]);
        float a8[8] = {p0.x, p0.y, p1.x, p1.y, p2.x, p2.y, p3.x, p3.y};
        int t = t0 + i;
        float m = a8[0];
#pragma unroll
        for (int j = 1; j < 8; j++) m = fmaxf(m, a8[j]);
#pragma unroll
        for (int off = 16; off >= 1; off >>= 1)
            m = fmaxf(m, __shfl_xor_sync(0xffffffffu, m, off));
        const float dgi = dg[t] + m;
        float4 o0, o1;
        o0.x = RATIO_F * (fexp(a8[0] - dgi) + KEPS_F);
        o0.y = RATIO_F * (fexp(a8[1] - dgi) + KEPS_F);
        o0.z = RATIO_F * (fexp(a8[2] - dgi) + KEPS_F);
        o0.w = RATIO_F * (fexp(a8[3] - dgi) + KEPS_F);
        o1.x = RATIO_F * (fexp(a8[4] - dgi) + KEPS_F);
        o1.y = RATIO_F * (fexp(a8[5] - dgi) + KEPS_F);
        o1.z = RATIO_F * (fexp(a8[6] - dgi) + KEPS_F);
        o1.w = RATIO_F * (fexp(a8[7] - dgi) + KEPS_F);
        *reinterpret_cast<float4*>(dst + t * 256 + r0) = o0;
        *reinterpret_cast<float4*>(dst + t * 256 + 128 + r0) = o1;
    }
}

// ---------------------------------------------------------------------------
__global__ void __launch_bounds__(256) k_featKC(const float* __restrict__ x,
                                                const float* __restrict__ v) {
    extern __shared__ float sm[];
    float* pT   = sm;                 // [64][256]; later E [t][r]
    float* xT   = sm + 16384;         // [64][68]
    float* sv   = sm + 20736;         // [64][64]
    float* dg   = sm + 24832;         // [64]
    float* wrd  = sm + 24896;         // [8]
    float* wra  = sm + 24904;         // [8]
    float* mcs  = sm + 24912;         // [1]
    float* E    = pT;
    const int tile = blockIdx.x, tid = threadIdx.x;
    const float* xg = x + (size_t)tile * (C_ * D_);
    float* dst = g_kf + (size_t)tile * (C_ * R_);

#pragma unroll
    for (int i = 0; i < 16; i++) {
        int i4 = tid + i * 256;
        reinterpret_cast<float4*>(pT)[i4] =
            reinterpret_cast<const float4*>(g_projT)[i4];
    }
#pragma unroll
    for (int i = 0; i < 4; i++) {
        int i4 = tid + i * 256;
        float4 vv = reinterpret_cast<const float4*>(xg)[i4];
        int t = (4 * i4) >> 6, kk = (4 * i4) & 63;
        xT[(kk + 0) * 68 + t] = vv.x;
        xT[(kk + 1) * 68 + t] = vv.y;
        xT[(kk + 2) * 68 + t] = vv.z;
        xT[(kk + 3) * 68 + t] = vv.w;
    }
    const float* vg = v + (size_t)tile * (C_ * D_);
#pragma unroll
    for (int i = 0; i < 4; i++) {
        int i4 = tid + i * 256;
        reinterpret_cast<float4*>(sv)[i4] =
            reinterpret_cast<const float4*>(vg)[i4];
    }
    __syncthreads();
    if (tid < 64) {
        float s = 0.f;
#pragma unroll
        for (int kk = 0; kk < 64; kk++) {
            float vv = xT[kk * 68 + tid];
            s = fmaf(vv, vv, s);
        }
        dg[tid] = DIAGC_F * s;
    }
    __syncthreads();

    const int tr = tid >> 5, tc = tid & 31;
    const int t0 = tr * 8, r0 = tc * 4;
    u64 acc[8][4];
#pragma unroll
    for (int i = 0; i < 8; i++)
#pragma unroll
        for (int j = 0; j < 4; j++) acc[i][j] = 0ull;

#pragma unroll 4
    for (int kk = 0; kk < 64; kk++) {
        float4 a0 = *reinterpret_cast<const float4*>(xT + kk * 68 + t0);
        float4 a1 = *reinterpret_cast<const float4*>(xT + kk * 68 + t0 + 4);
        ulonglong2 B0 = *reinterpret_cast<const ulonglong2*>(pT + kk * 256 + r0);
        ulonglong2 B1 = *reinterpret_cast<const ulonglong2*>(pT + kk * 256 + 128 + r0);
        u64 b[4] = {B0.x, B0.y, B1.x, B1.y};
        u64 ap[8] = {pk2(a0.x), pk2(a0.y), pk2(a0.z), pk2(a0.w),
                     pk2(a1.x), pk2(a1.y), pk2(a1.z), pk2(a1.w)};
#pragma unroll
        for (int i = 0; i < 8; i++)
#pragma unroll
            for (int j = 0; j < 4; j++) fma2(acc[i][j], ap[i], b[j]);
    }

    float bmd = -3.0e38f, bma = -3.0e38f;
#pragma unroll
    for (int i = 0; i < 8; i++) {
        float2 p0 = up2(acc[i][0]), p1 = up2(acc[i][1]);
        float2 p2 = up2(acc[i][2]), p3 = up2(acc[i][3]);
        float rm = fmaxf(fmaxf(fmaxf(p0.x, p0.y), fmaxf(p1.x, p1.y)),
                         fmaxf(fmaxf(p2.x, p2.y), fmaxf(p3.x, p3.y)));
        bmd = fmaxf(bmd, rm);
        bma = fmaxf(bma, rm - dg[t0 + i]);
    }
#pragma unroll
    for (int off = 16; off >= 1; off >>= 1) {
        bmd = fmaxf(bmd, __shfl_xor_sync(0xffffffffu, bmd, off));
        bma = fmaxf(bma, __shfl_xor_sync(0xffffffffu, bma, off));
    }
    if ((tid & 31) == 0) { wrd[tid >> 5] = bmd; wra[tid >> 5] = bma; }
    __syncthreads();
    if (tid == 0) {
        float md = wrd[0], ma = wra[0];
#pragma unroll
        for (int w = 1; w < 8; w++) {
            md = fmaxf(md, wrd[w]);
            ma = fmaxf(ma, wra[w]);
        }
        atomicMax(&g_maxkey, fkey(md));
        mcs[0] = ma;
    }
    __syncthreads();
    const float mc = mcs[0];

#pragma unroll
    for (int i = 0; i < 8; i++) {
        float2 p0 = up2(acc[i][0]), p1 = up2(acc[i][1]);
        float2 p2 = up2(acc[i][2]), p3 = up2(acc[i][3]);
        float a8[8] = {p0.x, p0.y, p1.x, p1.y, p2.x, p2.y, p3.x, p3.y};
        int t = t0 + i;
        const float sh = dg[t] + mc;
        float4 o0, o1;
        o0.x = fexp(a8[0] - sh); o0.y = fexp(a8[1] - sh);
        o0.z = fexp(a8[2] - sh); o0.w = fexp(a8[3] - sh);
        o1.x = fexp(a8[4] - sh); o1.y = fexp(a8[5] - sh);
        o1.z = fexp(a8[6] - sh); o1.w = fexp(a8[7] - sh);
        *reinterpret_cast<float4*>(E + t * 256 + r0) = o0;
        *reinterpret_cast<float4*>(E + t * 256 + 128 + r0) = o1;
        *reinterpret_cast<float4*>(dst + t * 256 + r0) = o0;
        *reinterpret_cast<float4*>(dst + t * 256 + 128 + r0) = o1;
    }
    __syncthreads();

    const int ri = tid >> 3, ei = tid & 7;
    const int rr0 = ri * 8, e0 = ei * 8;
    u64 acc2[8][4];
#pragma unroll
    for (int i = 0; i < 8; i++)
#pragma unroll
        for (int j = 0; j < 4; j++) acc2[i][j] = 0ull;

#pragma unroll 4
    for (int t = 0; t < 64; t++) {
        float4 a0 = *reinterpret_cast<const float4*>(E + t * 256 + rr0);
        float4 a1 = *reinterpret_cast<const float4*>(E + t * 256 + rr0 + 4);
        ulonglong2 B0 = *reinterpret_cast<const ulonglong2*>(sv + t * 64 + e0);
        ulonglong2 B1 = *reinterpret_cast<const ulonglong2*>(sv + t * 64 + e0 + 4);
        u64 b[4] = {B0.x, B0.y, B1.x, B1.y};
        u64 ap[8] = {pk2(a0.x), pk2(a0.y), pk2(a0.z), pk2(a0.w),
                     pk2(a1.x), pk2(a1.y), pk2(a1.z), pk2(a1.w)};
#pragma unroll
        for (int i = 0; i < 8; i++)
#pragma unroll
            for (int j = 0; j < 4; j++) fma2(acc2[i][j], ap[i], b[j]);
    }
    float zs = 0.f;
#pragma unroll 8
    for (int t = 0; t < 64; t++) zs += E[t * 256 + tid];

    float* So = g_sums + (size_t)tile * SSTRIDE;
#pragma unroll
    for (int i = 0; i < 8; i++) {
        int r = rr0 + i;
        float2 p0 = up2(acc2[i][0]), p1 = up2(acc2[i][1]);
        float2 p2 = up2(acc2[i][2]), p3 = up2(acc2[i][3]);
        *reinterpret_cast<float4*>(So + r * 64 + e0) =
            make_float4(p0.x, p0.y, p1.x, p1.y);
        *reinterpret_cast<float4*>(So + r * 64 + e0 + 4) =
            make_float4(p2.x, p2.y, p3.x, p3.y);
    }
    So[16384 + tid] = zs;
    if (tid < 64) {
        float vs = 0.f;
#pragma unroll 8
        for (int t = 0; t < 64; t++) vs += sv[t * 64 + tid];
        So[16640 + tid] = vs;
    }
    if (tid == 0) So[16704] = mc;
}

// ---------------------------------------------------------------------------
// Prefetched rescaling scan, strength-reduced: all addresses are running
// pointers bumped by SSTRIDE (no per-iteration multiplies).
__global__ void __launch_bounds__(256) k_scan() {
    const int head = blockIdx.x / 65, grp = blockIdx.x % 65;
    const int idx = grp * 256 + threadIdx.x;
    const bool isS = idx < 16384;
    const float stab = fdec(g_maxkey);
    const size_t base = (size_t)head * 64 * SSTRIDE;

    const float* pr = g_sums + base + idx;                      // raw (prefetch)
    const float* pm = g_sums + base + 16704;                    // m_c
    const float* pv = g_sums + base + (isS ? 16640 + (idx & 63) : 16704);
    float* pw = g_sums + base + idx;                            // write cursor

    float val[4];
#pragma unroll
    for (int p = 0; p < 4; p++) {
        float raw = pr[0];
        float mcv = pm[0];
        float vsv = isS ? pv[0] : 64.0f;
        val[p] = fmaf(RATIO_F * fexp(mcv - stab), raw, REPS_F * vsv);
        pr += SSTRIDE; pm += SSTRIDE; pv += SSTRIDE;
    }
    float run = 0.f;
#pragma unroll 4
    for (int c = 0; c < 64; c++) {
        float cur = val[c & 3];
        if (c + 4 < 64) {
            float raw = pr[0];
            float mcv = pm[0];
            float vsv = isS ? pv[0] : 64.0f;
            val[c & 3] = fmaf(RATIO_F * fexp(mcv - stab), raw, REPS_F * vsv);
            pr += SSTRIDE; pm += SSTRIDE; pv += SSTRIDE;
        }
        pw[0] = run;
        pw += SSTRIDE;
        run += cur;
    }
}

// ---------------------------------------------------------------------------
// Fused streaming k_out (48.5KB smem, 2 CTAs/SM):
// r in 4 chunks of 64; masked-QK^T, Q@S_pre, denominator share q loads.
// kp reconstructed as s1*E + REPS (no exp).
__global__ void __launch_bounds__(256, 2) k_out(const float* __restrict__ v,
                                                float* __restrict__ out) {
    extern __shared__ float sm[];
    float* q_c = sm;            // [64][64] swizzled; later A_s
    float* k_c = sm + 4096;     // [64][64] swizzled
    float* s_c = sm + 8192;     // [64][64] natural;  later v_s
    float* sz  = sm + 12288;    // [64]
    float* sDi = sz + 64;       // [64]
    float* A_s = q_c;
    float* v_s = s_c;

    const int tile = blockIdx.x, tid = threadIdx.x;
    const float4* qg4 = reinterpret_cast<const float4*>(g_qp + (size_t)tile * (C_ * R_));
    const float4* kg4 = reinterpret_cast<const float4*>(g_kf + (size_t)tile * (C_ * R_));
    const float*  Sg  = g_sums + (size_t)tile * SSTRIDE;
    const float4* Sg4 = reinterpret_cast<const float4*>(Sg);
    const float s1 = RATIO_F * fexp(Sg[16704] - fdec(g_maxkey));

    const int tg = tid >> 4;    // t = tg + 16*i
    const int mg = tid & 15;    // m = mg + 16*j ; e0 = mg*4
    const int e0 = mg * 4;

    u64 accA[4][4], accO[4][2];
#pragma unroll
    for (int i = 0; i < 4; i++) {
#pragma unroll
        for (int j = 0; j < 4; j++) accA[i][j] = 0ull;
        accO[i][0] = 0ull; accO[i][1] = 0ull;
    }
    float dp[4] = {0.f, 0.f, 0.f, 0.f};

#pragma unroll 1
    for (int rc = 0; rc < 4; rc++) {
        __syncthreads();
#pragma unroll
        for (int i = 0; i < 4; i++) {
            int i4 = tid + i * 256;
            int t = i4 >> 4, r4 = i4 & 15;
            int u = r4 ^ (t & 15);
            float4 a = qg4[t * 64 + rc * 16 + r4];
            *reinterpret_cast<float4*>(q_c + t * 64 + u * 4) = a;
            float4 b = kg4[t * 64 + rc * 16 + r4];
            b.x = fmaf(s1, b.x, REPS_F);
            b.y = fmaf(s1, b.y, REPS_F);
            b.z = fmaf(s1, b.z, REPS_F);
            b.w = fmaf(s1, b.w, REPS_F);
            *reinterpret_cast<float4*>(k_c + t * 64 + u * 4) = b;
            reinterpret_cast<float4*>(s_c)[i4] = Sg4[rc * 1024 + i4];
        }
        if (tid < 64) sz[tid] = Sg[16384 + rc * 64 + tid] + AEPS_F;
        __syncthreads();

#pragma unroll 2
        for (int rr = 0; rr < 16; rr++) {
            float4 aq[4];
            ulonglong2 bk[4], bs[4];
            const int qoff = (rr ^ tg) << 2;
#pragma unroll
            for (int i = 0; i < 4; i++)
                aq[i] = *reinterpret_cast<const float4*>(
                    q_c + (tg + 16 * i) * 64 + qoff);
#pragma unroll
            for (int j = 0; j < 4; j++)
                bk[j] = *reinterpret_cast<const ulonglong2*>(
                    k_c + (mg + 16 * j) * 64 + ((rr ^ mg) << 2));
#pragma unroll
            for (int c = 0; c < 4; c++)
                bs[c] = *reinterpret_cast<const ulonglong2*>(
                    s_c + (rr * 4 + c) * 64 + e0);
#pragma unroll
            for (int i = 0; i < 4; i++) {
                u64 alo = pkxy(aq[i].x, aq[i].y);
                u64 ahi = pkxy(aq[i].z, aq[i].w);
#pragma unroll
                for (int j = 0; j < 4; j++) {
                    fma2(accA[i][j], alo, bk[j].x);
                    fma2(accA[i][j], ahi, bk[j].y);
                }
                u64 p;
                p = pk2(aq[i].x); fma2(accO[i][0], p, bs[0].x); fma2(accO[i][1], p, bs[0].y);
                p = pk2(aq[i].y); fma2(accO[i][0], p, bs[1].x); fma2(accO[i][1], p, bs[1].y);
                p = pk2(aq[i].z); fma2(accO[i][0], p, bs[2].x); fma2(accO[i][1], p, bs[2].y);
                p = pk2(aq[i].w); fma2(accO[i][0], p, bs[3].x); fma2(accO[i][1], p, bs[3].y);
            }
            if (mg == 0) {
                const float* zz = sz + rr * 4;
#pragma unroll
                for (int i = 0; i < 4; i++) {
                    dp[i] = fmaf(aq[i].x, zz[0], dp[i]);
                    dp[i] = fmaf(aq[i].y, zz[1], dp[i]);
                    dp[i] = fmaf(aq[i].z, zz[2], dp[i]);
                    dp[i] = fmaf(aq[i].w, zz[3], dp[i]);
                }
            }
        }
    }
    __syncthreads();

    // mask A, denominators, A -> A_s(=q_c); v -> v_s(=s_c)
#pragma unroll
    for (int i = 0; i < 4; i++) {
        int t = tg + 16 * i;
        float af[4], p = 0.f;
#pragma unroll
        for (int j = 0; j < 4; j++) {
            float2 h = up2(accA[i][j]);
            af[j] = h.x + h.y;
            int m = mg + 16 * j;
            if (m > t) af[j] = 0.f;
            p += af[j];
        }
#pragma unroll
        for (int off = 1; off < 16; off <<= 1)
            p += __shfl_xor_sync(0xffffffffu, p, off, 16);
#pragma unroll
        for (int j = 0; j < 4; j++) {
            int m = mg + 16 * j;
            A_s[t * 64 + (((m >> 2) ^ (t & 15)) << 2) + (m & 3)] = af[j];
        }
        if (mg == 0) sDi[t] = 1.0f / (p + dp[i]);
    }
    const float4* vg4 = reinterpret_cast<const float4*>(v + (size_t)tile * (C_ * D_));
#pragma unroll
    for (int i = 0; i < 4; i++) {
        int i4 = tid + i * 256;
        reinterpret_cast<float4*>(v_s)[i4] = vg4[i4];
    }
    __syncthreads();

    // Phase B: O += A @ V
#pragma unroll 2
    for (int mm = 0; mm < 16; mm++) {
        float4 a[4];
        ulonglong2 b[4];
#pragma unroll
        for (int i = 0; i < 4; i++)
            a[i] = *reinterpret_cast<const float4*>(
                A_s + (tg + 16 * i) * 64 + ((mm ^ tg) << 2));
#pragma unroll
        for (int c = 0; c < 4; c++)
            b[c] = *reinterpret_cast<const ulonglong2*>(
                v_s + (mm * 4 + c) * 64 + e0);
#pragma unroll
        for (int i = 0; i < 4; i++) {
            u64 p;
            p = pk2(a[i].x); fma2(accO[i][0], p, b[0].x); fma2(accO[i][1], p, b[0].y);
            p = pk2(a[i].y); fma2(accO[i][0], p, b[1].x); fma2(accO[i][1], p, b[1].y);
            p = pk2(a[i].z); fma2(accO[i][0], p, b[2].x); fma2(accO[i][1], p, b[2].y);
            p = pk2(a[i].w); fma2(accO[i][0], p, b[3].x); fma2(accO[i][1], p, b[3].y);
        }
    }

    float* og = out + (size_t)tile * (C_ * D_);
#pragma unroll
    for (int i = 0; i < 4; i++) {
        int t = tg + 16 * i;
        float di = sDi[t];
        float2 h0 = up2(accO[i][0]), h1 = up2(accO[i][1]);
        *reinterpret_cast<float4*>(og + t * 64 + e0) =
            make_float4(h0.x * di, h0.y * di, h1.x * di, h1.y * di);
    }
}

// ---------------------------------------------------------------------------
extern "C" void kernel_launch(void* const* d_in, const int* in_sizes, int n_in,
                              void* d_out, int out_size) {
    const float* q    = (const float*)d_in[0];
    const float* k    = (const float*)d_in[1];
    const float* v    = (const float*)d_in[2];
    const float* proj = (const float*)d_in[3];
    float* out = (float*)d_out;

    const int SMEM_Q  = (16384 + 64 * 68 + 64) * 4;   // ~83 KB
    const int SMEM_KC = (24913 + 3) * 4;              // ~99.7 KB
    const int SMEM_O  = (4096 * 3 + 64 + 64) * 4;     // ~48.5 KB

    cudaFuncSetAttribute(k_featQ,  cudaFuncAttributeMaxDynamicSharedMemorySize, SMEM_Q);
    cudaFuncSetAttribute(k_featKC, cudaFuncAttributeMaxDynamicSharedMemorySize, SMEM_KC);
    cudaFuncSetAttribute(k_out,    cudaFuncAttributeMaxDynamicSharedMemorySize, SMEM_O);

    k_prep<<<1, 256>>>(proj);
    k_featQ<<<NTILES, 256, SMEM_Q>>>(q);
    k_featKC<<<NTILES, 256, SMEM_KC>>>(k, v);
    k_scan<<<1040, 256>>>();
    k_out<<<NTILES, 256, SMEM_O>>>(v, out);
}

// round 14
// speedup vs baseline: 1.5816x; 1.0149x over previous
#include <cuda_runtime.h>
#include <cuda_bf16.h>
#include <cstdint>

// ---------------------------------------------------------------------------
// Performer causal linear attention; FFMA2 cores; bf16 storage for qp and E.
// R14 = R13 architecture (k_featQ + fused k_featKC + prefetch k_scan +
//       streaming fused k_out), with g_qp/g_kf in bf16 (fp32 compute).
// b=2 h=8 n=4096 d=64 r=256 chunk=64 -> 65536 tokens, 1024 chunks
// g_sums record per tile (SSTRIDE=16768 floats):
//   [0,16384)  Sraw (later scanned S_pre)   [16384,16640) zraw (later z_pre)
//   [16640,16704) vsum                      [16704] m_c (not scanned)
// ---------------------------------------------------------------------------

constexpr int D_ = 64;
constexpr int R_ = 256;
constexpr int C_ = 64;
constexpr int NTILES = 1024;
constexpr int SSTRIDE = 16768;

__device__ __align__(16) float g_projT[D_ * R_];
__device__ __align__(16) __nv_bfloat16 g_qp[(size_t)NTILES * C_ * R_];
__device__ __align__(16) __nv_bfloat16 g_kf[(size_t)NTILES * C_ * R_];  // E
__device__ __align__(16) float g_sums[(size_t)NTILES * SSTRIDE];
__device__ unsigned g_maxkey;

#define NORM_F   0.35355339059327373f
#define DIAGC_F  0.0625f
#define RATIO_F  0.0625f
#define KEPS_F   1e-4f
#define AEPS_F   1e-6f
#define REPS_F   (RATIO_F * KEPS_F)

typedef unsigned long long u64;

__device__ __forceinline__ u64 pk2(float x) {
    u64 r; asm("mov.b64 %0, {%1, %1};" : "=l"(r) : "f"(x)); return r;
}
__device__ __forceinline__ u64 pkxy(float x, float y) {
    u64 r; asm("mov.b64 %0, {%1, %2};" : "=l"(r) : "f"(x), "f"(y)); return r;
}
__device__ __forceinline__ void fma2(u64& d, u64 a, u64 b) {
    asm("fma.rn.f32x2 %0, %1, %2, %0;" : "+l"(d) : "l"(a), "l"(b));
}
__device__ __forceinline__ float2 up2(u64 a) {
    float2 f; asm("mov.b64 {%0, %1}, %2;" : "=f"(f.x), "=f"(f.y) : "l"(a));
    return f;
}
__device__ __forceinline__ float fexp(float x) {
    x = fmaxf(x, -87.0f);
    float t  = x * 1.4426950408889634f;
    float nf = rintf(t);
    float f  = t - nf;
    float p  = 1.5403530393e-4f;
    p = fmaf(p, f, 1.3333558146e-3f);
    p = fmaf(p, f, 9.6181291076e-3f);
    p = fmaf(p, f, 5.5504108665e-2f);
    p = fmaf(p, f, 2.4022650696e-1f);
    p = fmaf(p, f, 6.9314718056e-1f);
    p = fmaf(p, f, 1.0f);
    int n = (int)nf;
    return p * __int_as_float((n + 127) << 23);
}
__device__ __forceinline__ unsigned fkey(float f) {
    unsigned u = __float_as_uint(f);
    return (u & 0x80000000u) ? ~u : (u | 0x80000000u);
}
__device__ __forceinline__ float fdec(unsigned k) {
    return (k & 0x80000000u) ? __uint_as_float(k ^ 0x80000000u)
                             : __uint_as_float(~k);
}
// pack two fp32 -> bf16x2 word; unpack bf16x2 word -> float2
__device__ __forceinline__ uint32_t bfp(float a, float b) {
    uint32_t r;
    asm("cvt.rn.bf16x2.f32 %0, %2, %1;" : "=r"(r) : "f"(a), "f"(b));
    return r;
}
__device__ __forceinline__ float2 bfu(uint32_t w) {
    __nv_bfloat162 h = *reinterpret_cast<__nv_bfloat162*>(&w);
    return __bfloat1622float2(h);
}

// ---------------------------------------------------------------------------
__global__ void k_prep(const float* __restrict__ proj) {
    int tid = threadIdx.x;
    for (int idx = tid; idx < D_ * R_; idx += blockDim.x) {
        int kk = idx / R_, rr = idx % R_;
        g_projT[idx] = proj[rr * D_ + kk] * NORM_F;
    }
    if (tid == 0) g_maxkey = 0u;
}

// ---------------------------------------------------------------------------
__global__ void __launch_bounds__(256) k_featQ(const float* __restrict__ x) {
    extern __shared__ float sm[];
    float* pT = sm;
    float* xT = sm + 16384;
    float* dg = xT + 64 * 68;
    const int tile = blockIdx.x, tid = threadIdx.x;
    const float* xg = x + (size_t)tile * (C_ * D_);
    __nv_bfloat16* dst = g_qp + (size_t)tile * (C_ * R_);

#pragma unroll
    for (int i = 0; i < 16; i++) {
        int i4 = tid + i * 256;
        reinterpret_cast<float4*>(pT)[i4] =
            reinterpret_cast<const float4*>(g_projT)[i4];
    }
#pragma unroll
    for (int i = 0; i < 4; i++) {
        int i4 = tid + i * 256;
        float4 vv = reinterpret_cast<const float4*>(xg)[i4];
        int t = (4 * i4) >> 6, kk = (4 * i4) & 63;
        xT[(kk + 0) * 68 + t] = vv.x;
        xT[(kk + 1) * 68 + t] = vv.y;
        xT[(kk + 2) * 68 + t] = vv.z;
        xT[(kk + 3) * 68 + t] = vv.w;
    }
    __syncthreads();
    if (tid < 64) {
        float s = 0.f;
#pragma unroll
        for (int kk = 0; kk < 64; kk++) {
            float vv = xT[kk * 68 + tid];
            s = fmaf(vv, vv, s);
        }
        dg[tid] = DIAGC_F * s;
    }
    __syncthreads();

    const int tr = tid >> 5, tc = tid & 31;
    const int t0 = tr * 8, r0 = tc * 4;
    u64 acc[8][4];
#pragma unroll
    for (int i = 0; i < 8; i++)
#pragma unroll
        for (int j = 0; j < 4; j++) acc[i][j] = 0ull;

#pragma unroll 4
    for (int kk = 0; kk < 64; kk++) {
        float4 a0 = *reinterpret_cast<const float4*>(xT + kk * 68 + t0);
        float4 a1 = *reinterpret_cast<const float4*>(xT + kk * 68 + t0 + 4);
        ulonglong2 B0 = *reinterpret_cast<const ulonglong2*>(pT + kk * 256 + r0);
        ulonglong2 B1 = *reinterpret_cast<const ulonglong2*>(pT + kk * 256 + 128 + r0);
        u64 b[4] = {B0.x, B0.y, B1.x, B1.y};
        u64 ap[8] = {pk2(a0.x), pk2(a0.y), pk2(a0.z), pk2(a0.w),
                     pk2(a1.x), pk2(a1.y), pk2(a1.z), pk2(a1.w)};
#pragma unroll
        for (int i = 0; i < 8; i++)
#pragma unroll
            for (int j = 0; j < 4; j++) fma2(acc[i][j], ap[i], b[j]);
    }

#pragma unroll
    for (int i = 0; i < 8; i++) {
        float2 p0 = up2(acc[i][0]), p1 = up2(acc[i][1]);
        float2 p2 = up2(acc[i][2]), p3 = up2(acc[i][3]);
        float a8[8] = {p0.x, p0.y, p1.x, p1.y, p2.x, p2.y, p3.x, p3.y};
        int t = t0 + i;
        float m = a8[0];
#pragma unroll
        for (int j = 1; j < 8; j++) m = fmaxf(m, a8[j]);
#pragma unroll
        for (int off = 16; off >= 1; off >>= 1)
            m = fmaxf(m, __shfl_xor_sync(0xffffffffu, m, off));
        const float dgi = dg[t] + m;
        float o0 = RATIO_F * (fexp(a8[0] - dgi) + KEPS_F);
        float o1 = RATIO_F * (fexp(a8[1] - dgi) + KEPS_F);
        float o2 = RATIO_F * (fexp(a8[2] - dgi) + KEPS_F);
        float o3 = RATIO_F * (fexp(a8[3] - dgi) + KEPS_F);
        float o4 = RATIO_F * (fexp(a8[4] - dgi) + KEPS_F);
        float o5 = RATIO_F * (fexp(a8[5] - dgi) + KEPS_F);
        float o6 = RATIO_F * (fexp(a8[6] - dgi) + KEPS_F);
        float o7 = RATIO_F * (fexp(a8[7] - dgi) + KEPS_F);
        *reinterpret_cast<uint2*>(dst + t * 256 + r0) =
            make_uint2(bfp(o0, o1), bfp(o2, o3));
        *reinterpret_cast<uint2*>(dst + t * 256 + 128 + r0) =
            make_uint2(bfp(o4, o5), bfp(o6, o7));
    }
}

// ---------------------------------------------------------------------------
__global__ void __launch_bounds__(256) k_featKC(const float* __restrict__ x,
                                                const float* __restrict__ v) {
    extern __shared__ float sm[];
    float* pT   = sm;                 // [64][256]; later E [t][r]
    float* xT   = sm + 16384;         // [64][68]
    float* sv   = sm + 20736;         // [64][64]
    float* dg   = sm + 24832;         // [64]
    float* wrd  = sm + 24896;         // [8]
    float* wra  = sm + 24904;         // [8]
    float* mcs  = sm + 24912;         // [1]
    float* E    = pT;
    const int tile = blockIdx.x, tid = threadIdx.x;
    const float* xg = x + (size_t)tile * (C_ * D_);
    __nv_bfloat16* dst = g_kf + (size_t)tile * (C_ * R_);

#pragma unroll
    for (int i = 0; i < 16; i++) {
        int i4 = tid + i * 256;
        reinterpret_cast<float4*>(pT)[i4] =
            reinterpret_cast<const float4*>(g_projT)[i4];
    }
#pragma unroll
    for (int i = 0; i < 4; i++) {
        int i4 = tid + i * 256;
        float4 vv = reinterpret_cast<const float4*>(xg)[i4];
        int t = (4 * i4) >> 6, kk = (4 * i4) & 63;
        xT[(kk + 0) * 68 + t] = vv.x;
        xT[(kk + 1) * 68 + t] = vv.y;
        xT[(kk + 2) * 68 + t] = vv.z;
        xT[(kk + 3) * 68 + t] = vv.w;
    }
    const float* vg = v + (size_t)tile * (C_ * D_);
#pragma unroll
    for (int i = 0; i < 4; i++) {
        int i4 = tid + i * 256;
        reinterpret_cast<float4*>(sv)[i4] =
            reinterpret_cast<const float4*>(vg)[i4];
    }
    __syncthreads();
    if (tid < 64) {
        float s = 0.f;
#pragma unroll
        for (int kk = 0; kk < 64; kk++) {
            float vv = xT[kk * 68 + tid];
            s = fmaf(vv, vv, s);
        }
        dg[tid] = DIAGC_F * s;
    }
    __syncthreads();

    const int tr = tid >> 5, tc = tid & 31;
    const int t0 = tr * 8, r0 = tc * 4;
    u64 acc[8][4];
#pragma unroll
    for (int i = 0; i < 8; i++)
#pragma unroll
        for (int j = 0; j < 4; j++) acc[i][j] = 0ull;

#pragma unroll 4
    for (int kk = 0; kk < 64; kk++) {
        float4 a0 = *reinterpret_cast<const float4*>(xT + kk * 68 + t0);
        float4 a1 = *reinterpret_cast<const float4*>(xT + kk * 68 + t0 + 4);
        ulonglong2 B0 = *reinterpret_cast<const ulonglong2*>(pT + kk * 256 + r0);
        ulonglong2 B1 = *reinterpret_cast<const ulonglong2*>(pT + kk * 256 + 128 + r0);
        u64 b[4] = {B0.x, B0.y, B1.x, B1.y};
        u64 ap[8] = {pk2(a0.x), pk2(a0.y), pk2(a0.z), pk2(a0.w),
                     pk2(a1.x), pk2(a1.y), pk2(a1.z), pk2(a1.w)};
#pragma unroll
        for (int i = 0; i < 8; i++)
#pragma unroll
            for (int j = 0; j < 4; j++) fma2(acc[i][j], ap[i], b[j]);
    }

    float bmd = -3.0e38f, bma = -3.0e38f;
#pragma unroll
    for (int i = 0; i < 8; i++) {
        float2 p0 = up2(acc[i][0]), p1 = up2(acc[i][1]);
        float2 p2 = up2(acc[i][2]), p3 = up2(acc[i][3]);
        float rm = fmaxf(fmaxf(fmaxf(p0.x, p0.y), fmaxf(p1.x, p1.y)),
                         fmaxf(fmaxf(p2.x, p2.y), fmaxf(p3.x, p3.y)));
        bmd = fmaxf(bmd, rm);
        bma = fmaxf(bma, rm - dg[t0 + i]);
    }
#pragma unroll
    for (int off = 16; off >= 1; off >>= 1) {
        bmd = fmaxf(bmd, __shfl_xor_sync(0xffffffffu, bmd, off));
        bma = fmaxf(bma, __shfl_xor_sync(0xffffffffu, bma, off));
    }
    if ((tid & 31) == 0) { wrd[tid >> 5] = bmd; wra[tid >> 5] = bma; }
    __syncthreads();
    if (tid == 0) {
        float md = wrd[0], ma = wra[0];
#pragma unroll
        for (int w = 1; w < 8; w++) {
            md = fmaxf(md, wrd[w]);
            ma = fmaxf(ma, wra[w]);
        }
        atomicMax(&g_maxkey, fkey(md));
        mcs[0] = ma;
    }
    __syncthreads();
    const float mc = mcs[0];

#pragma unroll
    for (int i = 0; i < 8; i++) {
        float2 p0 = up2(acc[i][0]), p1 = up2(acc[i][1]);
        float2 p2 = up2(acc[i][2]), p3 = up2(acc[i][3]);
        float a8[8] = {p0.x, p0.y, p1.x, p1.y, p2.x, p2.y, p3.x, p3.y};
        int t = t0 + i;
        const float sh = dg[t] + mc;
        float e0v = fexp(a8[0] - sh), e1v = fexp(a8[1] - sh);
        float e2v = fexp(a8[2] - sh), e3v = fexp(a8[3] - sh);
        float e4v = fexp(a8[4] - sh), e5v = fexp(a8[5] - sh);
        float e6v = fexp(a8[6] - sh), e7v = fexp(a8[7] - sh);
        *reinterpret_cast<float4*>(E + t * 256 + r0) =
            make_float4(e0v, e1v, e2v, e3v);
        *reinterpret_cast<float4*>(E + t * 256 + 128 + r0) =
            make_float4(e4v, e5v, e6v, e7v);
        *reinterpret_cast<uint2*>(dst + t * 256 + r0) =
            make_uint2(bfp(e0v, e1v), bfp(e2v, e3v));
        *reinterpret_cast<uint2*>(dst + t * 256 + 128 + r0) =
            make_uint2(bfp(e4v, e5v), bfp(e6v, e7v));
    }
    __syncthreads();

    const int ri = tid >> 3, ei = tid & 7;
    const int rr0 = ri * 8, e0 = ei * 8;
    u64 acc2[8][4];
#pragma unroll
    for (int i = 0; i < 8; i++)
#pragma unroll
        for (int j = 0; j < 4; j++) acc2[i][j] = 0ull;

#pragma unroll 4
    for (int t = 0; t < 64; t++) {
        float4 a0 = *reinterpret_cast<const float4*>(E + t * 256 + rr0);
        float4 a1 = *reinterpret_cast<const float4*>(E + t * 256 + rr0 + 4);
        ulonglong2 B0 = *reinterpret_cast<const ulonglong2*>(sv + t * 64 + e0);
        ulonglong2 B1 = *reinterpret_cast<const ulonglong2*>(sv + t * 64 + e0 + 4);
        u64 b[4] = {B0.x, B0.y, B1.x, B1.y};
        u64 ap[8] = {pk2(a0.x), pk2(a0.y), pk2(a0.z), pk2(a0.w),
                     pk2(a1.x), pk2(a1.y), pk2(a1.z), pk2(a1.w)};
#pragma unroll
        for (int i = 0; i < 8; i++)
#pragma unroll
            for (int j = 0; j < 4; j++) fma2(acc2[i][j], ap[i], b[j]);
    }
    float zs = 0.f;
#pragma unroll 8
    for (int t = 0; t < 64; t++) zs += E[t * 256 + tid];

    float* So = g_sums + (size_t)tile * SSTRIDE;
#pragma unroll
    for (int i = 0; i < 8; i++) {
        int r = rr0 + i;
        float2 p0 = up2(acc2[i][0]), p1 = up2(acc2[i][1]);
        float2 p2 = up2(acc2[i][2]), p3 = up2(acc2[i][3]);
        *reinterpret_cast<float4*>(So + r * 64 + e0) =
            make_float4(p0.x, p0.y, p1.x, p1.y);
        *reinterpret_cast<float4*>(So + r * 64 + e0 + 4) =
            make_float4(p2.x, p2.y, p3.x, p3.y);
    }
    So[16384 + tid] = zs;
    if (tid < 64) {
        float vs = 0.f;
#pragma unroll 8
        for (int t = 0; t < 64; t++) vs += sv[t * 64 + tid];
        So[16640 + tid] = vs;
    }
    if (tid == 0) So[16704] = mc;
}

// ---------------------------------------------------------------------------
// Prefetched rescaling scan (pointer increments, MLP=4).
__global__ void __launch_bounds__(256) k_scan() {
    const int head = blockIdx.x / 65, grp = blockIdx.x % 65;
    const int idx = grp * 256 + threadIdx.x;
    const bool isS = idx < 16384;
    const float stab = fdec(g_maxkey);
    const size_t base = (size_t)head * 64 * SSTRIDE;

    const float* pr = g_sums + base + idx;
    const float* pm = g_sums + base + 16704;
    const float* pv = g_sums + base + (isS ? 16640 + (idx & 63) : 16704);
    float* pw = g_sums + base + idx;

    float val[4];
#pragma unroll
    for (int p = 0; p < 4; p++) {
        float raw = pr[0];
        float mcv = pm[0];
        float vsv = isS ? pv[0] : 64.0f;
        val[p] = fmaf(RATIO_F * fexp(mcv - stab), raw, REPS_F * vsv);
        pr += SSTRIDE; pm += SSTRIDE; pv += SSTRIDE;
    }
    float run = 0.f;
#pragma unroll 4
    for (int c = 0; c < 64; c++) {
        float cur = val[c & 3];
        if (c + 4 < 64) {
            float raw = pr[0];
            float mcv = pm[0];
            float vsv = isS ? pv[0] : 64.0f;
            val[c & 3] = fmaf(RATIO_F * fexp(mcv - stab), raw, REPS_F * vsv);
            pr += SSTRIDE; pm += SSTRIDE; pv += SSTRIDE;
        }
        pw[0] = run;
        pw += SSTRIDE;
        run += cur;
    }
}

// ---------------------------------------------------------------------------
// Fused streaming k_out (48.5KB smem, 2 CTAs/SM); bf16 qp/E loads.
__global__ void __launch_bounds__(256, 2) k_out(const float* __restrict__ v,
                                                float* __restrict__ out) {
    extern __shared__ float sm[];
    float* q_c = sm;            // [64][64] swizzled; later A_s
    float* k_c = sm + 4096;     // [64][64] swizzled
    float* s_c = sm + 8192;     // [64][64] natural;  later v_s
    float* sz  = sm + 12288;    // [64]
    float* sDi = sz + 64;       // [64]
    float* A_s = q_c;
    float* v_s = s_c;

    const int tile = blockIdx.x, tid = threadIdx.x;
    const uint2* qg2 = reinterpret_cast<const uint2*>(g_qp + (size_t)tile * (C_ * R_));
    const uint2* kg2 = reinterpret_cast<const uint2*>(g_kf + (size_t)tile * (C_ * R_));
    const float*  Sg  = g_sums + (size_t)tile * SSTRIDE;
    const float4* Sg4 = reinterpret_cast<const float4*>(Sg);
    const float s1 = RATIO_F * fexp(Sg[16704] - fdec(g_maxkey));

    const int tg = tid >> 4;    // t = tg + 16*i
    const int mg = tid & 15;    // m = mg + 16*j ; e0 = mg*4
    const int e0 = mg * 4;

    u64 accA[4][4], accO[4][2];
#pragma unroll
    for (int i = 0; i < 4; i++) {
#pragma unroll
        for (int j = 0; j < 4; j++) accA[i][j] = 0ull;
        accO[i][0] = 0ull; accO[i][1] = 0ull;
    }
    float dp[4] = {0.f, 0.f, 0.f, 0.f};

#pragma unroll 1
    for (int rc = 0; rc < 4; rc++) {
        __syncthreads();
#pragma unroll
        for (int i = 0; i < 4; i++) {
            int i4 = tid + i * 256;
            int t = i4 >> 4, r4 = i4 & 15;
            int u = r4 ^ (t & 15);
            uint2 qa = qg2[t * 64 + rc * 16 + r4];
            float2 qa0 = bfu(qa.x), qa1 = bfu(qa.y);
            *reinterpret_cast<float4*>(q_c + t * 64 + u * 4) =
                make_float4(qa0.x, qa0.y, qa1.x, qa1.y);
            uint2 kb = kg2[t * 64 + rc * 16 + r4];
            float2 kb0 = bfu(kb.x), kb1 = bfu(kb.y);
            float4 b;
            b.x = fmaf(s1, kb0.x, REPS_F);
            b.y = fmaf(s1, kb0.y, REPS_F);
            b.z = fmaf(s1, kb1.x, REPS_F);
            b.w = fmaf(s1, kb1.y, REPS_F);
            *reinterpret_cast<float4*>(k_c + t * 64 + u * 4) = b;
            reinterpret_cast<float4*>(s_c)[i4] = Sg4[rc * 1024 + i4];
        }
        if (tid < 64) sz[tid] = Sg[16384 + rc * 64 + tid] + AEPS_F;
        __syncthreads();

#pragma unroll 2
        for (int rr = 0; rr < 16; rr++) {
            float4 aq[4];
            ulonglong2 bk[4], bs[4];
            const int qoff = (rr ^ tg) << 2;
#pragma unroll
            for (int i = 0; i < 4; i++)
                aq[i] = *reinterpret_cast<const float4*>(
                    q_c + (tg + 16 * i) * 64 + qoff);
#pragma unroll
            for (int j = 0; j < 4; j++)
                bk[j] = *reinterpret_cast<const ulonglong2*>(
                    k_c + (mg + 16 * j) * 64 + ((rr ^ mg) << 2));
#pragma unroll
            for (int c = 0; c < 4; c++)
                bs[c] = *reinterpret_cast<const ulonglong2*>(
                    s_c + (rr * 4 + c) * 64 + e0);
#pragma unroll
            for (int i = 0; i < 4; i++) {
                u64 alo = pkxy(aq[i].x, aq[i].y);
                u64 ahi = pkxy(aq[i].z, aq[i].w);
#pragma unroll
                for (int j = 0; j < 4; j++) {
                    fma2(accA[i][j], alo, bk[j].x);
                    fma2(accA[i][j], ahi, bk[j].y);
                }
                u64 p;
                p = pk2(aq[i].x); fma2(accO[i][0], p, bs[0].x); fma2(accO[i][1], p, bs[0].y);
                p = pk2(aq[i].y); fma2(accO[i][0], p, bs[1].x); fma2(accO[i][1], p, bs[1].y);
                p = pk2(aq[i].z); fma2(accO[i][0], p, bs[2].x); fma2(accO[i][1], p, bs[2].y);
                p = pk2(aq[i].w); fma2(accO[i][0], p, bs[3].x); fma2(accO[i][1], p, bs[3].y);
            }
            if (mg == 0) {
                const float* zz = sz + rr * 4;
#pragma unroll
                for (int i = 0; i < 4; i++) {
                    dp[i] = fmaf(aq[i].x, zz[0], dp[i]);
                    dp[i] = fmaf(aq[i].y, zz[1], dp[i]);
                    dp[i] = fmaf(aq[i].z, zz[2], dp[i]);
                    dp[i] = fmaf(aq[i].w, zz[3], dp[i]);
                }
            }
        }
    }
    __syncthreads();

    // mask A, denominators, A -> A_s(=q_c); v -> v_s(=s_c)
#pragma unroll
    for (int i = 0; i < 4; i++) {
        int t = tg + 16 * i;
        float af[4], p = 0.f;
#pragma unroll
        for (int j = 0; j < 4; j++) {
            float2 h = up2(accA[i][j]);
            af[j] = h.x + h.y;
            int m = mg + 16 * j;
            if (m > t) af[j] = 0.f;
            p += af[j];
        }
#pragma unroll
        for (int off = 1; off < 16; off <<= 1)
            p += __shfl_xor_sync(0xffffffffu, p, off, 16);
#pragma unroll
        for (int j = 0; j < 4; j++) {
            int m = mg + 16 * j;
            A_s[t * 64 + (((m >> 2) ^ (t & 15)) << 2) + (m & 3)] = af[j];
        }
        if (mg == 0) sDi[t] = 1.0f / (p + dp[i]);
    }
    const float4* vg4 = reinterpret_cast<const float4*>(v + (size_t)tile * (C_ * D_));
#pragma unroll
    for (int i = 0; i < 4; i++) {
        int i4 = tid + i * 256;
        reinterpret_cast<float4*>(v_s)[i4] = vg4[i4];
    }
    __syncthreads();

    // Phase B: O += A @ V
#pragma unroll 2
    for (int mm = 0; mm < 16; mm++) {
        float4 a[4];
        ulonglong2 b[4];
#pragma unroll
        for (int i = 0; i < 4; i++)
            a[i] = *reinterpret_cast<const float4*>(
                A_s + (tg + 16 * i) * 64 + ((mm ^ tg) << 2));
#pragma unroll
        for (int c = 0; c < 4; c++)
            b[c] = *reinterpret_cast<const ulonglong2*>(
                v_s + (mm * 4 + c) * 64 + e0);
#pragma unroll
        for (int i = 0; i < 4; i++) {
            u64 p;
            p = pk2(a[i].x); fma2(accO[i][0], p, b[0].x); fma2(accO[i][1], p, b[0].y);
            p = pk2(a[i].y); fma2(accO[i][0], p, b[1].x); fma2(accO[i][1], p, b[1].y);
            p = pk2(a[i].z); fma2(accO[i][0], p, b[2].x); fma2(accO[i][1], p, b[2].y);
            p = pk2(a[i].w); fma2(accO[i][0], p, b[3].x); fma2(accO[i][1], p, b[3].y);
        }
    }

    float* og = out + (size_t)tile * (C_ * D_);
#pragma unroll
    for (int i = 0; i < 4; i++) {
        int t = tg + 16 * i;
        float di = sDi[t];
        float2 h0 = up2(accO[i][0]), h1 = up2(accO[i][1]);
        *reinterpret_cast<float4*>(og + t * 64 + e0) =
            make_float4(h0.x * di, h0.y * di, h1.x * di, h1.y * di);
    }
}

// ---------------------------------------------------------------------------
extern "C" void kernel_launch(void* const* d_in, const int* in_sizes, int n_in,
                              void* d_out, int out_size) {
    const float* q    = (const float*)d_in[0];
    const float* k    = (const float*)d_in[1];
    const float* v    = (const float*)d_in[2];
    const float* proj = (const float*)d_in[3];
    float* out = (float*)d_out;

    const int SMEM_Q  = (16384 + 64 * 68 + 64) * 4;   // ~83 KB
    const int SMEM_KC = (24913 + 3) * 4;              // ~99.7 KB
    const int SMEM_O  = (4096 * 3 + 64 + 64) * 4;     // ~48.5 KB

    cudaFuncSetAttribute(k_featQ,  cudaFuncAttributeMaxDynamicSharedMemorySize, SMEM_Q);
    cudaFuncSetAttribute(k_featKC, cudaFuncAttributeMaxDynamicSharedMemorySize, SMEM_KC);
    cudaFuncSetAttribute(k_out,    cudaFuncAttributeMaxDynamicSharedMemorySize, SMEM_O);

    k_prep<<<1, 256>>>(proj);
    k_featQ<<<NTILES, 256, SMEM_Q>>>(q);
    k_featKC<<<NTILES, 256, SMEM_KC>>>(k, v);
    k_scan<<<1040, 256>>>();
    k_out<<<NTILES, 256, SMEM_O>>>(v, out);
}

// round 16
// speedup vs baseline: 1.5859x; 1.0027x over previous
#include <cuda_runtime.h>
#include <cuda_bf16.h>
#include <cstdint>

// ---------------------------------------------------------------------------
// Performer causal linear attention; FFMA2 cores; bf16 storage for qp and E.
// R16 = R14 verbatim (proven best: 335.5us, rel_err 1.44e-5).
// Architecture: k_featQ + fused k_featKC + prefetch k_scan (fp32 state) +
// streaming fused k_out. bf16 ONLY for qp/E (S_pre/z must stay fp32 — R15).
// b=2 h=8 n=4096 d=64 r=256 chunk=64 -> 65536 tokens, 1024 chunks
// g_sums record per tile (SSTRIDE=16768 floats):
//   [0,16384) Sraw->S_pre  [16384,16640) zraw->z_pre
//   [16640,16704) vsum     [16704] m_c (not scanned)
// ---------------------------------------------------------------------------

constexpr int D_ = 64;
constexpr int R_ = 256;
constexpr int C_ = 64;
constexpr int NTILES = 1024;
constexpr int SSTRIDE = 16768;

__device__ __align__(16) float g_projT[D_ * R_];
__device__ __align__(16) __nv_bfloat16 g_qp[(size_t)NTILES * C_ * R_];
__device__ __align__(16) __nv_bfloat16 g_kf[(size_t)NTILES * C_ * R_];  // E
__device__ __align__(16) float g_sums[(size_t)NTILES * SSTRIDE];
__device__ unsigned g_maxkey;

#define NORM_F   0.35355339059327373f
#define DIAGC_F  0.0625f
#define RATIO_F  0.0625f
#define KEPS_F   1e-4f
#define AEPS_F   1e-6f
#define REPS_F   (RATIO_F * KEPS_F)

typedef unsigned long long u64;

__device__ __forceinline__ u64 pk2(float x) {
    u64 r; asm("mov.b64 %0, {%1, %1};" : "=l"(r) : "f"(x)); return r;
}
__device__ __forceinline__ u64 pkxy(float x, float y) {
    u64 r; asm("mov.b64 %0, {%1, %2};" : "=l"(r) : "f"(x), "f"(y)); return r;
}
__device__ __forceinline__ void fma2(u64& d, u64 a, u64 b) {
    asm("fma.rn.f32x2 %0, %1, %2, %0;" : "+l"(d) : "l"(a), "l"(b));
}
__device__ __forceinline__ float2 up2(u64 a) {
    float2 f; asm("mov.b64 {%0, %1}, %2;" : "=f"(f.x), "=f"(f.y) : "l"(a));
    return f;
}
__device__ __forceinline__ float fexp(float x) {
    x = fmaxf(x, -87.0f);
    float t  = x * 1.4426950408889634f;
    float nf = rintf(t);
    float f  = t - nf;
    float p  = 1.5403530393e-4f;
    p = fmaf(p, f, 1.3333558146e-3f);
    p = fmaf(p, f, 9.6181291076e-3f);
    p = fmaf(p, f, 5.5504108665e-2f);
    p = fmaf(p, f, 2.4022650696e-1f);
    p = fmaf(p, f, 6.9314718056e-1f);
    p = fmaf(p, f, 1.0f);
    int n = (int)nf;
    return p * __int_as_float((n + 127) << 23);
}
__device__ __forceinline__ unsigned fkey(float f) {
    unsigned u = __float_as_uint(f);
    return (u & 0x80000000u) ? ~u : (u | 0x80000000u);
}
__device__ __forceinline__ float fdec(unsigned k) {
    return (k & 0x80000000u) ? __uint_as_float(k ^ 0x80000000u)
                             : __uint_as_float(~k);
}
__device__ __forceinline__ uint32_t bfp(float a, float b) {
    uint32_t r;
    asm("cvt.rn.bf16x2.f32 %0, %2, %1;" : "=r"(r) : "f"(a), "f"(b));
    return r;
}
__device__ __forceinline__ float2 bfu(uint32_t w) {
    __nv_bfloat162 h = *reinterpret_cast<__nv_bfloat162*>(&w);
    return __bfloat1622float2(h);
}

// ---------------------------------------------------------------------------
__global__ void k_prep(const float* __restrict__ proj) {
    int tid = threadIdx.x;
    for (int idx = tid; idx < D_ * R_; idx += blockDim.x) {
        int kk = idx / R_, rr = idx % R_;
        g_projT[idx] = proj[rr * D_ + kk] * NORM_F;
    }
    if (tid == 0) g_maxkey = 0u;
}

// ---------------------------------------------------------------------------
__global__ void __launch_bounds__(256) k_featQ(const float* __restrict__ x) {
    extern __shared__ float sm[];
    float* pT = sm;
    float* xT = sm + 16384;
    float* dg = xT + 64 * 68;
    const int tile = blockIdx.x, tid = threadIdx.x;
    const float* xg = x + (size_t)tile * (C_ * D_);
    __nv_bfloat16* dst = g_qp + (size_t)tile * (C_ * R_);

#pragma unroll
    for (int i = 0; i < 16; i++) {
        int i4 = tid + i * 256;
        reinterpret_cast<float4*>(pT)[i4] =
            reinterpret_cast<const float4*>(g_projT)[i4];
    }
#pragma unroll
    for (int i = 0; i < 4; i++) {
        int i4 = tid + i * 256;
        float4 vv = reinterpret_cast<const float4*>(xg)[i4];
        int t = (4 * i4) >> 6, kk = (4 * i4) & 63;
        xT[(kk + 0) * 68 + t] = vv.x;
        xT[(kk + 1) * 68 + t] = vv.y;
        xT[(kk + 2) * 68 + t] = vv.z;
        xT[(kk + 3) * 68 + t] = vv.w;
    }
    __syncthreads();
    if (tid < 64) {
        float s = 0.f;
#pragma unroll
        for (int kk = 0; kk < 64; kk++) {
            float vv = xT[kk * 68 + tid];
            s = fmaf(vv, vv, s);
        }
        dg[tid] = DIAGC_F * s;
    }
    __syncthreads();

    const int tr = tid >> 5, tc = tid & 31;
    const int t0 = tr * 8, r0 = tc * 4;
    u64 acc[8][4];
#pragma unroll
    for (int i = 0; i < 8; i++)
#pragma unroll
        for (int j = 0; j < 4; j++) acc[i][j] = 0ull;

#pragma unroll 4
    for (int kk = 0; kk < 64; kk++) {
        float4 a0 = *reinterpret_cast<const float4*>(xT + kk * 68 + t0);
        float4 a1 = *reinterpret_cast<const float4*>(xT + kk * 68 + t0 + 4);
        ulonglong2 B0 = *reinterpret_cast<const ulonglong2*>(pT + kk * 256 + r0);
        ulonglong2 B1 = *reinterpret_cast<const ulonglong2*>(pT + kk * 256 + 128 + r0);
        u64 b[4] = {B0.x, B0.y, B1.x, B1.y};
        u64 ap[8] = {pk2(a0.x), pk2(a0.y), pk2(a0.z), pk2(a0.w),
                     pk2(a1.x), pk2(a1.y), pk2(a1.z), pk2(a1.w)};
#pragma unroll
        for (int i = 0; i < 8; i++)
#pragma unroll
            for (int j = 0; j < 4; j++) fma2(acc[i][j], ap[i], b[j]);
    }

#pragma unroll
    for (int i = 0; i < 8; i++) {
        float2 p0 = up2(acc[i][0]), p1 = up2(acc[i][1]);
        float2 p2 = up2(acc[i][2]), p3 = up2(acc[i][3]);
        float a8[8] = {p0.x, p0.y, p1.x, p1.y, p2.x, p2.y, p3.x, p3.y};
        int t = t0 + i;
        float m = a8[0];
#pragma unroll
        for (int j = 1; j < 8; j++) m = fmaxf(m, a8[j]);
#pragma unroll
        for (int off = 16; off >= 1; off >>= 1)
            m = fmaxf(m, __shfl_xor_sync(0xffffffffu, m, off));
        const float dgi = dg[t] + m;
        float o0 = RATIO_F * (fexp(a8[0] - dgi) + KEPS_F);
        float o1 = RATIO_F * (fexp(a8[1] - dgi) + KEPS_F);
        float o2 = RATIO_F * (fexp(a8[2] - dgi) + KEPS_F);
        float o3 = RATIO_F * (fexp(a8[3] - dgi) + KEPS_F);
        float o4 = RATIO_F * (fexp(a8[4] - dgi) + KEPS_F);
        float o5 = RATIO_F * (fexp(a8[5] - dgi) + KEPS_F);
        float o6 = RATIO_F * (fexp(a8[6] - dgi) + KEPS_F);
        float o7 = RATIO_F * (fexp(a8[7] - dgi) + KEPS_F);
        *reinterpret_cast<uint2*>(dst + t * 256 + r0) =
            make_uint2(bfp(o0, o1), bfp(o2, o3));
        *reinterpret_cast<uint2*>(dst + t * 256 + 128 + r0) =
            make_uint2(bfp(o4, o5), bfp(o6, o7));
    }
}

// ---------------------------------------------------------------------------
__global__ void __launch_bounds__(256) k_featKC(const float* __restrict__ x,
                                                const float* __restrict__ v) {
    extern __shared__ float sm[];
    float* pT   = sm;                 // [64][256]; later E [t][r]
    float* xT   = sm + 16384;         // [64][68]
    float* sv   = sm + 20736;         // [64][64]
    float* dg   = sm + 24832;         // [64]
    float* wrd  = sm + 24896;         // [8]
    float* wra  = sm + 24904;         // [8]
    float* mcs  = sm + 24912;         // [1]
    float* E    = pT;
    const int tile = blockIdx.x, tid = threadIdx.x;
    const float* xg = x + (size_t)tile * (C_ * D_);
    __nv_bfloat16* dst = g_kf + (size_t)tile * (C_ * R_);

#pragma unroll
    for (int i = 0; i < 16; i++) {
        int i4 = tid + i * 256;
        reinterpret_cast<float4*>(pT)[i4] =
            reinterpret_cast<const float4*>(g_projT)[i4];
    }
#pragma unroll
    for (int i = 0; i < 4; i++) {
        int i4 = tid + i * 256;
        float4 vv = reinterpret_cast<const float4*>(xg)[i4];
        int t = (4 * i4) >> 6, kk = (4 * i4) & 63;
        xT[(kk + 0) * 68 + t] = vv.x;
        xT[(kk + 1) * 68 + t] = vv.y;
        xT[(kk + 2) * 68 + t] = vv.z;
        xT[(kk + 3) * 68 + t] = vv.w;
    }
    const float* vg = v + (size_t)tile * (C_ * D_);
#pragma unroll
    for (int i = 0; i < 4; i++) {
        int i4 = tid + i * 256;
        reinterpret_cast<float4*>(sv)[i4] =
            reinterpret_cast<const float4*>(vg)[i4];
    }
    __syncthreads();
    if (tid < 64) {
        float s = 0.f;
#pragma unroll
        for (int kk = 0; kk < 64; kk++) {
            float vv = xT[kk * 68 + tid];
            s = fmaf(vv, vv, s);
        }
        dg[tid] = DIAGC_F * s;
    }
    __syncthreads();

    const int tr = tid >> 5, tc = tid & 31;
    const int t0 = tr * 8, r0 = tc * 4;
    u64 acc[8][4];
#pragma unroll
    for (int i = 0; i < 8; i++)
#pragma unroll
        for (int j = 0; j < 4; j++) acc[i][j] = 0ull;

#pragma unroll 4
    for (int kk = 0; kk < 64; kk++) {
        float4 a0 = *reinterpret_cast<const float4*>(xT + kk * 68 + t0);
        float4 a1 = *reinterpret_cast<const float4*>(xT + kk * 68 + t0 + 4);
        ulonglong2 B0 = *reinterpret_cast<const ulonglong2*>(pT + kk * 256 + r0);
        ulonglong2 B1 = *reinterpret_cast<const ulonglong2*>(pT + kk * 256 + 128 + r0);
        u64 b[4] = {B0.x, B0.y, B1.x, B1.y};
        u64 ap[8] = {pk2(a0.x), pk2(a0.y), pk2(a0.z), pk2(a0.w),
                     pk2(a1.x), pk2(a1.y), pk2(a1.z), pk2(a1.w)};
#pragma unroll
        for (int i = 0; i < 8; i++)
#pragma unroll
            for (int j = 0; j < 4; j++) fma2(acc[i][j], ap[i], b[j]);
    }

    float bmd = -3.0e38f, bma = -3.0e38f;
#pragma unroll
    for (int i = 0; i < 8; i++) {
        float2 p0 = up2(acc[i][0]), p1 = up2(acc[i][1]);
        float2 p2 = up2(acc[i][2]), p3 = up2(acc[i][3]);
        float rm = fmaxf(fmaxf(fmaxf(p0.x, p0.y), fmaxf(p1.x, p1.y)),
                         fmaxf(fmaxf(p2.x, p2.y), fmaxf(p3.x, p3.y)));
        bmd = fmaxf(bmd, rm);
        bma = fmaxf(bma, rm - dg[t0 + i]);
    }
#pragma unroll
    for (int off = 16; off >= 1; off >>= 1) {
        bmd = fmaxf(bmd, __shfl_xor_sync(0xffffffffu, bmd, off));
        bma = fmaxf(bma, __shfl_xor_sync(0xffffffffu, bma, off));
    }
    if ((tid & 31) == 0) { wrd[tid >> 5] = bmd; wra[tid >> 5] = bma; }
    __syncthreads();
    if (tid == 0) {
        float md = wrd[0], ma = wra[0];
#pragma unroll
        for (int w = 1; w < 8; w++) {
            md = fmaxf(md, wrd[w]);
            ma = fmaxf(ma, wra[w]);
        }
        atomicMax(&g_maxkey, fkey(md));
        mcs[0] = ma;
    }
    __syncthreads();
    const float mc = mcs[0];

#pragma unroll
    for (int i = 0; i < 8; i++) {
        float2 p0 = up2(acc[i][0]), p1 = up2(acc[i][1]);
        float2 p2 = up2(acc[i][2]), p3 = up2(acc[i][3]);
        float a8[8] = {p0.x, p0.y, p1.x, p1.y, p2.x, p2.y, p3.x, p3.y};
        int t = t0 + i;
        const float sh = dg[t] + mc;
        float e0v = fexp(a8[0] - sh), e1v = fexp(a8[1] - sh);
        float e2v = fexp(a8[2] - sh), e3v = fexp(a8[3] - sh);
        float e4v = fexp(a8[4] - sh), e5v = fexp(a8[5] - sh);
        float e6v = fexp(a8[6] - sh), e7v = fexp(a8[7] - sh);
        *reinterpret_cast<float4*>(E + t * 256 + r0) =
            make_float4(e0v, e1v, e2v, e3v);
        *reinterpret_cast<float4*>(E + t * 256 + 128 + r0) =
            make_float4(e4v, e5v, e6v, e7v);
        *reinterpret_cast<uint2*>(dst + t * 256 + r0) =
            make_uint2(bfp(e0v, e1v), bfp(e2v, e3v));
        *reinterpret_cast<uint2*>(dst + t * 256 + 128 + r0) =
            make_uint2(bfp(e4v, e5v), bfp(e6v, e7v));
    }
    __syncthreads();

    const int ri = tid >> 3, ei = tid & 7;
    const int rr0 = ri * 8, e0 = ei * 8;
    u64 acc2[8][4];
#pragma unroll
    for (int i = 0; i < 8; i++)
#pragma unroll
        for (int j = 0; j < 4; j++) acc2[i][j] = 0ull;

#pragma unroll 4
    for (int t = 0; t < 64; t++) {
        float4 a0 = *reinterpret_cast<const float4*>(E + t * 256 + rr0);
        float4 a1 = *reinterpret_cast<const float4*>(E + t * 256 + rr0 + 4);
        ulonglong2 B0 = *reinterpret_cast<const ulonglong2*>(sv + t * 64 + e0);
        ulonglong2 B1 = *reinterpret_cast<const ulonglong2*>(sv + t * 64 + e0 + 4);
        u64 b[4] = {B0.x, B0.y, B1.x, B1.y};
        u64 ap[8] = {pk2(a0.x), pk2(a0.y), pk2(a0.z), pk2(a0.w),
                     pk2(a1.x), pk2(a1.y), pk2(a1.z), pk2(a1.w)};
#pragma unroll
        for (int i = 0; i < 8; i++)
#pragma unroll
            for (int j = 0; j < 4; j++) fma2(acc2[i][j], ap[i], b[j]);
    }
    float zs = 0.f;
#pragma unroll 8
    for (int t = 0; t < 64; t++) zs += E[t * 256 + tid];

    float* So = g_sums + (size_t)tile * SSTRIDE;
#pragma unroll
    for (int i = 0; i < 8; i++) {
        int r = rr0 + i;
        float2 p0 = up2(acc2[i][0]), p1 = up2(acc2[i][1]);
        float2 p2 = up2(acc2[i][2]), p3 = up2(acc2[i][3]);
        *reinterpret_cast<float4*>(So + r * 64 + e0) =
            make_float4(p0.x, p0.y, p1.x, p1.y);
        *reinterpret_cast<float4*>(So + r * 64 + e0 + 4) =
            make_float4(p2.x, p2.y, p3.x, p3.y);
    }
    So[16384 + tid] = zs;
    if (tid < 64) {
        float vs = 0.f;
#pragma unroll 8
        for (int t = 0; t < 64; t++) vs += sv[t * 64 + tid];
        So[16640 + tid] = vs;
    }
    if (tid == 0) So[16704] = mc;
}

// ---------------------------------------------------------------------------
// Prefetched rescaling scan (pointer increments, MLP=4). fp32 state.
__global__ void __launch_bounds__(256) k_scan() {
    const int head = blockIdx.x / 65, grp = blockIdx.x % 65;
    const int idx = grp * 256 + threadIdx.x;
    const bool isS = idx < 16384;
    const float stab = fdec(g_maxkey);
    const size_t base = (size_t)head * 64 * SSTRIDE;

    const float* pr = g_sums + base + idx;
    const float* pm = g_sums + base + 16704;
    const float* pv = g_sums + base + (isS ? 16640 + (idx & 63) : 16704);
    float* pw = g_sums + base + idx;

    float val[4];
#pragma unroll
    for (int p = 0; p < 4; p++) {
        float raw = pr[0];
        float mcv = pm[0];
        float vsv = isS ? pv[0] : 64.0f;
        val[p] = fmaf(RATIO_F * fexp(mcv - stab), raw, REPS_F * vsv);
        pr += SSTRIDE; pm += SSTRIDE; pv += SSTRIDE;
    }
    float run = 0.f;
#pragma unroll 4
    for (int c = 0; c < 64; c++) {
        float cur = val[c & 3];
        if (c + 4 < 64) {
            float raw = pr[0];
            float mcv = pm[0];
            float vsv = isS ? pv[0] : 64.0f;
            val[c & 3] = fmaf(RATIO_F * fexp(mcv - stab), raw, REPS_F * vsv);
            pr += SSTRIDE; pm += SSTRIDE; pv += SSTRIDE;
        }
        pw[0] = run;
        pw += SSTRIDE;
        run += cur;
    }
}

// ---------------------------------------------------------------------------
// Fused streaming k_out (48.5KB smem, 2 CTAs/SM); bf16 qp/E loads.
__global__ void __launch_bounds__(256, 2) k_out(const float* __restrict__ v,
                                                float* __restrict__ out) {
    extern __shared__ float sm[];
    float* q_c = sm;            // [64][64] swizzled; later A_s
    float* k_c = sm + 4096;     // [64][64] swizzled
    float* s_c = sm + 8192;     // [64][64] natural;  later v_s
    float* sz  = sm + 12288;    // [64]
    float* sDi = sz + 64;       // [64]
    float* A_s = q_c;
    float* v_s = s_c;

    const int tile = blockIdx.x, tid = threadIdx.x;
    const uint2* qg2 = reinterpret_cast<const uint2*>(g_qp + (size_t)tile * (C_ * R_));
    const uint2* kg2 = reinterpret_cast<const uint2*>(g_kf + (size_t)tile * (C_ * R_));
    const float*  Sg  = g_sums + (size_t)tile * SSTRIDE;
    const float4* Sg4 = reinterpret_cast<const float4*>(Sg);
    const float s1 = RATIO_F * fexp(Sg[16704] - fdec(g_maxkey));

    const int tg = tid >> 4;    // t = tg + 16*i
    const int mg = tid & 15;    // m = mg + 16*j ; e0 = mg*4
    const int e0 = mg * 4;

    u64 accA[4][4], accO[4][2];
#pragma unroll
    for (int i = 0; i < 4; i++) {
#pragma unroll
        for (int j = 0; j < 4; j++) accA[i][j] = 0ull;
        accO[i][0] = 0ull; accO[i][1] = 0ull;
    }
    float dp[4] = {0.f, 0.f, 0.f, 0.f};

#pragma unroll 1
    for (int rc = 0; rc < 4; rc++) {
        __syncthreads();
#pragma unroll
        for (int i = 0; i < 4; i++) {
            int i4 = tid + i * 256;
            int t = i4 >> 4, r4 = i4 & 15;
            int u = r4 ^ (t & 15);
            uint2 qa = qg2[t * 64 + rc * 16 + r4];
            float2 qa0 = bfu(qa.x), qa1 = bfu(qa.y);
            *reinterpret_cast<float4*>(q_c + t * 64 + u * 4) =
                make_float4(qa0.x, qa0.y, qa1.x, qa1.y);
            uint2 kb = kg2[t * 64 + rc * 16 + r4];
            float2 kb0 = bfu(kb.x), kb1 = bfu(kb.y);
            float4 b;
            b.x = fmaf(s1, kb0.x, REPS_F);
            b.y = fmaf(s1, kb0.y, REPS_F);
            b.z = fmaf(s1, kb1.x, REPS_F);
            b.w = fmaf(s1, kb1.y, REPS_F);
            *reinterpret_cast<float4*>(k_c + t * 64 + u * 4) = b;
            reinterpret_cast<float4*>(s_c)[i4] = Sg4[rc * 1024 + i4];
        }
        if (tid < 64) sz[tid] = Sg[16384 + rc * 64 + tid] + AEPS_F;
        __syncthreads();

#pragma unroll 2
        for (int rr = 0; rr < 16; rr++) {
            float4 aq[4];
            ulonglong2 bk[4], bs[4];
            const int qoff = (rr ^ tg) << 2;
#pragma unroll
            for (int i = 0; i < 4; i++)
                aq[i] = *reinterpret_cast<const float4*>(
                    q_c + (tg + 16 * i) * 64 + qoff);
#pragma unroll
            for (int j = 0; j < 4; j++)
                bk[j] = *reinterpret_cast<const ulonglong2*>(
                    k_c + (mg + 16 * j) * 64 + ((rr ^ mg) << 2));
#pragma unroll
            for (int c = 0; c < 4; c++)
                bs[c] = *reinterpret_cast<const ulonglong2*>(
                    s_c + (rr * 4 + c) * 64 + e0);
#pragma unroll
            for (int i = 0; i < 4; i++) {
                u64 alo = pkxy(aq[i].x, aq[i].y);
                u64 ahi = pkxy(aq[i].z, aq[i].w);
#pragma unroll
                for (int j = 0; j < 4; j++) {
                    fma2(accA[i][j], alo, bk[j].x);
                    fma2(accA[i][j], ahi, bk[j].y);
                }
                u64 p;
                p = pk2(aq[i].x); fma2(accO[i][0], p, bs[0].x); fma2(accO[i][1], p, bs[0].y);
                p = pk2(aq[i].y); fma2(accO[i][0], p, bs[1].x); fma2(accO[i][1], p, bs[1].y);
                p = pk2(aq[i].z); fma2(accO[i][0], p, bs[2].x); fma2(accO[i][1], p, bs[2].y);
                p = pk2(aq[i].w); fma2(accO[i][0], p, bs[3].x); fma2(accO[i][1], p, bs[3].y);
            }
            if (mg == 0) {
                const float* zz = sz + rr * 4;
#pragma unroll
                for (int i = 0; i < 4; i++) {
                    dp[i] = fmaf(aq[i].x, zz[0], dp[i]);
                    dp[i] = fmaf(aq[i].y, zz[1], dp[i]);
                    dp[i] = fmaf(aq[i].z, zz[2], dp[i]);
                    dp[i] = fmaf(aq[i].w, zz[3], dp[i]);
                }
            }
        }
    }
    __syncthreads();

    // mask A, denominators, A -> A_s(=q_c); v -> v_s(=s_c)
#pragma unroll
    for (int i = 0; i < 4; i++) {
        int t = tg + 16 * i;
        float af[4], p = 0.f;
#pragma unroll
        for (int j = 0; j < 4; j++) {
            float2 h = up2(accA[i][j]);
            af[j] = h.x + h.y;
            int m = mg + 16 * j;
            if (m > t) af[j] = 0.f;
            p += af[j];
        }
#pragma unroll
        for (int off = 1; off < 16; off <<= 1)
            p += __shfl_xor_sync(0xffffffffu, p, off, 16);
#pragma unroll
        for (int j = 0; j < 4; j++) {
            int m = mg + 16 * j;
            A_s[t * 64 + (((m >> 2) ^ (t & 15)) << 2) + (m & 3)] = af[j];
        }
        if (mg == 0) sDi[t] = 1.0f / (p + dp[i]);
    }
    const float4* vg4 = reinterpret_cast<const float4*>(v + (size_t)tile * (C_ * D_));
#pragma unroll
    for (int i = 0; i < 4; i++) {
        int i4 = tid + i * 256;
        reinterpret_cast<float4*>(v_s)[i4] = vg4[i4];
    }
    __syncthreads();

    // Phase B: O += A @ V
#pragma unroll 2
    for (int mm = 0; mm < 16; mm++) {
        float4 a[4];
        ulonglong2 b[4];
#pragma unroll
        for (int i = 0; i < 4; i++)
            a[i] = *reinterpret_cast<const float4*>(
                A_s + (tg + 16 * i) * 64 + ((mm ^ tg) << 2));
#pragma unroll
        for (int c = 0; c < 4; c++)
            b[c] = *reinterpret_cast<const ulonglong2*>(
                v_s + (mm * 4 + c) * 64 + e0);
#pragma unroll
        for (int i = 0; i < 4; i++) {
            u64 p;
            p = pk2(a[i].x); fma2(accO[i][0], p, b[0].x); fma2(accO[i][1], p, b[0].y);
            p = pk2(a[i].y); fma2(accO[i][0], p, b[1].x); fma2(accO[i][1], p, b[1].y);
            p = pk2(a[i].z); fma2(accO[i][0], p, b[2].x); fma2(accO[i][1], p, b[2].y);
            p = pk2(a[i].w); fma2(accO[i][0], p, b[3].x); fma2(accO[i][1], p, b[3].y);
        }
    }

    float* og = out + (size_t)tile * (C_ * D_);
#pragma unroll
    for (int i = 0; i < 4; i++) {
        int t = tg + 16 * i;
        float di = sDi[t];
        float2 h0 = up2(accO[i][0]), h1 = up2(accO[i][1]);
        *reinterpret_cast<float4*>(og + t * 64 + e0) =
            make_float4(h0.x * di, h0.y * di, h1.x * di, h1.y * di);
    }
}

// ---------------------------------------------------------------------------
extern "C" void kernel_launch(void* const* d_in, const int* in_sizes, int n_in,
                              void* d_out, int out_size) {
    const float* q    = (const float*)d_in[0];
    const float* k    = (const float*)d_in[1];
    const float* v    = (const float*)d_in[2];
    const float* proj = (const float*)d_in[3];
    float* out = (float*)d_out;

    const int SMEM_Q  = (16384 + 64 * 68 + 64) * 4;   // ~83 KB
    const int SMEM_KC = (24913 + 3) * 4;              // ~99.7 KB
    const int SMEM_O  = (4096 * 3 + 64 + 64) * 4;     // ~48.5 KB

    cudaFuncSetAttribute(k_featQ,  cudaFuncAttributeMaxDynamicSharedMemorySize, SMEM_Q);
    cudaFuncSetAttribute(k_featKC, cudaFuncAttributeMaxDynamicSharedMemorySize, SMEM_KC);
    cudaFuncSetAttribute(k_out,    cudaFuncAttributeMaxDynamicSharedMemorySize, SMEM_O);

    k_prep<<<1, 256>>>(proj);
    k_featQ<<<NTILES, 256, SMEM_Q>>>(q);
    k_featKC<<<NTILES, 256, SMEM_KC>>>(k, v);
    k_scan<<<1040, 256>>>();
    k_out<<<NTILES, 256, SMEM_O>>>(v, out);
}